// round 11
// baseline (speedup 1.0000x reference)
#include <cuda_runtime.h>
#include <cuda_fp16.h>
#include <math.h>

#define NN 50000
#define EE 600000
#define DD 128
#define ELLS 96                    // ELL row stride (max supported degree)

// ---------------- scratch (device globals; no allocation allowed) ----------
__device__ float g_dinv[NN];
__device__ int   g_cnt[NN];          // per-dst fill cursor / final count
__device__ uint2 g_cell[NN * ELLS];  // ELL slot: (src index, raw ew bits)
__device__ unsigned g_h16[NN * 64];  // raw messages h as half2 pairs
__device__ float g_agg[NN * DD];     // aggregated features (layer-0 output, f32)
__device__ float g_sc[2 * DD];       // folded BN scale per layer
__device__ float g_sh[2 * DD];       // folded BN shift (incl. bias) per layer
__device__ float g_alpha;            // sigmoid(act_params[0])

// ---------------- prep kernels (side stream) --------------------------------
__global__ void k_zero() {
    int i = blockIdx.x * blockDim.x + threadIdx.x;
    if (i < NN) g_cnt[i] = 0;
}

// ELL slot fill with (src, raw ew); 4 independent edges per thread (MLP)
__global__ void k_fill(const int* __restrict__ src, const int* __restrict__ dst,
                       const float* __restrict__ ew) {
    int t = blockIdx.x * blockDim.x + threadIdx.x;
    int stride = gridDim.x * blockDim.x;
    int   dd[4], ss[4];
    float ww[4];
    bool  vv[4];
#pragma unroll
    for (int i = 0; i < 4; i++) {
        int e = t + i * stride;
        vv[i] = (e < EE);
        if (vv[i]) {
            dd[i] = dst[e];
            ss[i] = src[e];
            ww[i] = ew[e];
        }
    }
#pragma unroll
    for (int i = 0; i < 4; i++) {
        if (vv[i]) {
            int c = atomicAdd(&g_cnt[dd[i]], 1);
            if (c < ELLS)
                g_cell[dd[i] * ELLS + c] = make_uint2((unsigned)ss[i],
                                                      __float_as_uint(ww[i]));
        }
    }
}

// warp per node: weighted degree = sum of raw slot weights; dinv = rsqrt(deg+1)
__global__ void k_dinv() {
    int t = blockIdx.x * blockDim.x + threadIdx.x;
    int node = t >> 5;
    int lane = t & 31;
    if (node >= NN) return;
    int cnt = g_cnt[node];
    if (cnt > ELLS) cnt = ELLS;
    int beg = node * ELLS;
    float s = 0.f;
    for (int j = lane; j < cnt; j += 32)
        s += __uint_as_float(g_cell[beg + j].y);
#pragma unroll
    for (int off = 16; off > 0; off >>= 1)
        s += __shfl_down_sync(0xFFFFFFFFu, s, off);
    if (lane == 0) g_dinv[node] = rsqrtf(s + 1.0f);   // +1 = self-loop weight
}

__global__ void k_bnprep(const float* __restrict__ b0, const float* __restrict__ ga0,
                         const float* __restrict__ be0, const float* __restrict__ m0,
                         const float* __restrict__ v0,
                         const float* __restrict__ b1, const float* __restrict__ ga1,
                         const float* __restrict__ be1, const float* __restrict__ m1,
                         const float* __restrict__ v1,
                         const float* __restrict__ act) {
    int t = threadIdx.x;
    if (t < DD) {
        float sc = ga0[t] * rsqrtf(v0[t] + 1e-5f);
        g_sc[t] = sc;
        g_sh[t] = be0[t] + (b0[t] - m0[t]) * sc;
    } else if (t < 2 * DD) {
        int c = t - DD;
        float sc = ga1[c] * rsqrtf(v1[c] + 1e-5f);
        g_sc[t] = sc;
        g_sh[t] = be1[c] + (b1[c] - m1[c]) * sc;
    }
    if (t == 0) g_alpha = 1.0f / (1.0f + expf(-act[0]));
}

// ---------------- tf32 tensor-core GEMM -------------------------------------
// H16 = A' @ W   (raw fp16 messages; graph-independent)
// A' = A (PRE_POST=0) or adaptive-act(BN0(A)) applied during staging.
#define SMS 132                                    // smem row stride (floats)
#define GEMM_SMEM ((64 * SMS + 128 * SMS) * 4)     // As + Ws

__device__ __forceinline__ unsigned f2tf32(float f) {
    unsigned u;
    asm("cvt.rna.tf32.f32 %0, %1;" : "=r"(u) : "f"(f));
    return u;
}

template <int PRE_POST>
__global__ __launch_bounds__(256) void k_gemm(const float* __restrict__ A,
                                              const float* __restrict__ W,
                                              unsigned* __restrict__ H16, int n) {
    extern __shared__ unsigned sm[];
    unsigned* As = sm;              // [64][SMS]
    unsigned* Ws = sm + 64 * SMS;   // [128][SMS]

    int tid = threadIdx.x;
    int row0 = blockIdx.x * 64;

    // ---- stage W (tf32-converted) ----
    const float4* W4 = (const float4*)W;
#pragma unroll
    for (int i = 0; i < 16; i++) {
        int idx = tid + i * 256;        // 4096 float4 = 128 rows x 32
        int r = idx >> 5, c = idx & 31;
        float4 v = W4[idx];
        uint4 u = make_uint4(f2tf32(v.x), f2tf32(v.y), f2tf32(v.z), f2tf32(v.w));
        *(uint4*)&Ws[r * SMS + c * 4] = u;
    }

    // ---- stage A tile (+ fused BN0 + adaptive act for layer 1), tf32 ----
    float alpha = g_alpha;
    const float4* A4 = (const float4*)A;
#pragma unroll
    for (int i = 0; i < 8; i++) {
        int idx = tid + i * 256;        // 2048 float4 = 64 rows x 32
        int r = idx >> 5, c = idx & 31;
        float4 v = make_float4(0.f, 0.f, 0.f, 0.f);
        if (row0 + r < n) v = A4[(size_t)(row0 + r) * 32 + c];
        if (PRE_POST) {
            float* pv = (float*)&v;
#pragma unroll
            for (int j = 0; j < 4; j++) {
                float t = pv[j] * g_sc[c * 4 + j] + g_sh[c * 4 + j];
                float relu = fmaxf(t, 0.f);
                float gelu = 0.5f * t * (1.f + erff(t * 0.70710678118654752f));
                pv[j] = alpha * relu + (1.f - alpha) * gelu;
            }
        }
        uint4 u = make_uint4(f2tf32(v.x), f2tf32(v.y), f2tf32(v.z), f2tf32(v.w));
        *(uint4*)&As[r * SMS + c * 4] = u;
    }
    __syncthreads();

    int wid = tid >> 5;
    int lane = tid & 31;
    int rw = (wid & 3) * 16;       // row band within tile
    int cw = (wid >> 2) * 64;      // col half
    int q = lane >> 2;             // 0..7
    int m = lane & 3;              // 0..3

    float acc[8][4];
#pragma unroll
    for (int nt = 0; nt < 8; nt++)
#pragma unroll
        for (int j = 0; j < 4; j++) acc[nt][j] = 0.f;

#pragma unroll
    for (int kt = 0; kt < 16; kt++) {
        int k0 = kt * 8;
        const unsigned* Ar = &As[(rw + q) * SMS + k0 + m];
        unsigned a0 = Ar[0];
        unsigned a2 = Ar[4];
        unsigned a1 = Ar[8 * SMS];
        unsigned a3 = Ar[8 * SMS + 4];
#pragma unroll
        for (int nt = 0; nt < 8; nt++) {
            int n0 = cw + nt * 8;
            unsigned b0 = Ws[(k0 + m) * SMS + n0 + q];
            unsigned b1 = Ws[(k0 + m + 4) * SMS + n0 + q];
            asm("mma.sync.aligned.m16n8k8.row.col.f32.tf32.tf32.f32 "
                "{%0,%1,%2,%3}, {%4,%5,%6,%7}, {%8,%9}, {%0,%1,%2,%3};"
                : "+f"(acc[nt][0]), "+f"(acc[nt][1]), "+f"(acc[nt][2]), "+f"(acc[nt][3])
                : "r"(a0), "r"(a1), "r"(a2), "r"(a3), "r"(b0), "r"(b1));
        }
    }

    // ---- epilogue: store raw fp16 message pairs ----
    int r_lo = row0 + rw + q;       // rows r_lo and r_lo+8
#pragma unroll
    for (int nt = 0; nt < 8; nt++) {
        int col = cw + nt * 8 + 2 * m;
        if (r_lo < n) {
            __half2 hv = __floats2half2_rn(acc[nt][0], acc[nt][1]);
            H16[(size_t)r_lo * 64 + (col >> 1)] = *(unsigned*)&hv;
        }
        if (r_lo + 8 < n) {
            __half2 hv = __floats2half2_rn(acc[nt][2], acc[nt][3]);
            H16[(size_t)(r_lo + 8) * 64 + (col >> 1)] = *(unsigned*)&hv;
        }
    }
}

// ---------------- gather: one warp per destination node --------------------
// inner = dinv_d*m[d] + sum_j (ew_j*dinv_sj)*m[src_j];  out = dinv_d * inner
// (normalization applied in-gather; no precomputed edge norms needed)
template <int POST>
__global__ __launch_bounds__(256) void k_gather(const uint2* __restrict__ h,
                                                float4* __restrict__ out) {
    int t = blockIdx.x * blockDim.x + threadIdx.x;
    int node = t >> 5;
    int lane = t & 31;
    if (node >= NN) return;

    int beg = node * ELLS;
    int cnt = g_cnt[node];
    if (cnt > ELLS) cnt = ELLS;
    int end = beg + cnt;

    float dn = g_dinv[node];
    uint2 sr = h[(size_t)node * 32 + lane];
    float2 slo = __half22float2(*(__half2*)&sr.x);
    float2 shi = __half22float2(*(__half2*)&sr.y);
    float4 acc = make_float4(slo.x * dn, slo.y * dn, shi.x * dn, shi.y * dn);

    int j = beg;
    for (; j + 3 < end; j += 4) {
        uint2 e0 = __ldg(&g_cell[j]);
        uint2 e1 = __ldg(&g_cell[j + 1]);
        uint2 e2 = __ldg(&g_cell[j + 2]);
        uint2 e3 = __ldg(&g_cell[j + 3]);
        float w0 = __uint_as_float(e0.y) * __ldg(&g_dinv[e0.x]);
        float w1 = __uint_as_float(e1.y) * __ldg(&g_dinv[e1.x]);
        float w2 = __uint_as_float(e2.y) * __ldg(&g_dinv[e2.x]);
        float w3 = __uint_as_float(e3.y) * __ldg(&g_dinv[e3.x]);
        uint2 r0 = h[(size_t)e0.x * 32 + lane];
        uint2 r1 = h[(size_t)e1.x * 32 + lane];
        uint2 r2 = h[(size_t)e2.x * 32 + lane];
        uint2 r3 = h[(size_t)e3.x * 32 + lane];
        float2 l0 = __half22float2(*(__half2*)&r0.x), h0 = __half22float2(*(__half2*)&r0.y);
        float2 l1 = __half22float2(*(__half2*)&r1.x), h1 = __half22float2(*(__half2*)&r1.y);
        float2 l2 = __half22float2(*(__half2*)&r2.x), h2 = __half22float2(*(__half2*)&r2.y);
        float2 l3 = __half22float2(*(__half2*)&r3.x), h3 = __half22float2(*(__half2*)&r3.y);
        acc.x += w0 * l0.x + w1 * l1.x + w2 * l2.x + w3 * l3.x;
        acc.y += w0 * l0.y + w1 * l1.y + w2 * l2.y + w3 * l3.y;
        acc.z += w0 * h0.x + w1 * h1.x + w2 * h2.x + w3 * h3.x;
        acc.w += w0 * h0.y + w1 * h1.y + w2 * h2.y + w3 * h3.y;
    }
    for (; j < end; j++) {
        uint2 e = __ldg(&g_cell[j]);
        float w = __uint_as_float(e.y) * __ldg(&g_dinv[e.x]);
        uint2 r = h[(size_t)e.x * 32 + lane];
        float2 lo = __half22float2(*(__half2*)&r.x);
        float2 hi = __half22float2(*(__half2*)&r.y);
        acc.x += w * lo.x;
        acc.y += w * lo.y;
        acc.z += w * hi.x;
        acc.w += w * hi.y;
    }

    acc.x *= dn; acc.y *= dn; acc.z *= dn; acc.w *= dn;

    if (POST) {
        int c0 = lane * 4 + DD;   // layer-1 BN params
        acc.x = acc.x * g_sc[c0 + 0] + g_sh[c0 + 0];
        acc.y = acc.y * g_sc[c0 + 1] + g_sh[c0 + 1];
        acc.z = acc.z * g_sc[c0 + 2] + g_sh[c0 + 2];
        acc.w = acc.w * g_sc[c0 + 3] + g_sh[c0 + 3];
    }
    out[(size_t)node * 32 + lane] = acc;
}

// ---------------- launch ----------------------------------------------------
extern "C" void kernel_launch(void* const* d_in, const int* in_sizes, int n_in,
                              void* d_out, int out_size) {
    const float* x  = (const float*)d_in[0];
    const int*   ei = (const int*)d_in[1];     // [2,E]: row0=src, row1=dst
    const float* ew = (const float*)d_in[2];
    const float* W0 = (const float*)d_in[3];
    const float* b0 = (const float*)d_in[4];
    const float* W1 = (const float*)d_in[5];
    const float* b1 = (const float*)d_in[6];
    const float* ga0 = (const float*)d_in[7];
    const float* be0 = (const float*)d_in[8];
    const float* m0  = (const float*)d_in[9];
    const float* v0  = (const float*)d_in[10];
    const float* ga1 = (const float*)d_in[11];
    const float* be1 = (const float*)d_in[12];
    const float* m1  = (const float*)d_in[13];
    const float* v1  = (const float*)d_in[14];
    const float* act = (const float*)d_in[15];
    float* out = (float*)d_out;

    const int* src = ei;
    const int* dst = ei + EE;

    unsigned* hD; cudaGetSymbolAddress((void**)&hD, g_h16);
    float* aggD;  cudaGetSymbolAddress((void**)&aggD, g_agg);

    cudaFuncSetAttribute(k_gemm<0>, cudaFuncAttributeMaxDynamicSharedMemorySize, GEMM_SMEM);
    cudaFuncSetAttribute(k_gemm<1>, cudaFuncAttributeMaxDynamicSharedMemorySize, GEMM_SMEM);

    // side stream + fork/join events (created once; capture-safe fork pattern)
    static cudaStream_t sA = nullptr;
    static cudaEvent_t evFork = nullptr, evJoin = nullptr;
    if (sA == nullptr) {
        cudaStreamCreateWithFlags(&sA, cudaStreamNonBlocking);
        cudaEventCreateWithFlags(&evFork, cudaEventDisableTiming);
        cudaEventCreateWithFlags(&evJoin, cudaEventDisableTiming);
    }

    const int B = 256;
    int gN    = (NN + B - 1) / B;
    int gFill = (EE + 4 * B - 1) / (4 * B);
    int gGth  = (NN * 32 + B - 1) / B;
    int gGemm = (NN + 63) / 64;

    // ---- fork: graph prep on side stream, concurrent with layer-0 GEMM ----
    cudaEventRecord(evFork, 0);
    cudaStreamWaitEvent(sA, evFork, 0);
    k_zero<<<gN, B, 0, sA>>>();
    k_fill<<<gFill, B, 0, sA>>>(src, dst, ew);
    k_dinv<<<gGth, B, 0, sA>>>();
    cudaEventRecord(evJoin, sA);

    // ---- main stream: bn prep + layer-0 GEMM (graph-independent) ----
    k_bnprep<<<1, 256>>>(b0, ga0, be0, m0, v0, b1, ga1, be1, m1, v1, act);
    k_gemm<0><<<gGemm, B, GEMM_SMEM>>>(x, W0, hD, NN);

    // ---- join: gather needs ELL + dinv ----
    cudaStreamWaitEvent(0, evJoin, 0);
    k_gather<0><<<gGth, B>>>((const uint2*)hD, (float4*)aggD);

    // layer 1
    k_gemm<1><<<gGemm, B, GEMM_SMEM>>>(aggD, W1, hD, NN);
    k_gather<1><<<gGth, B>>>((const uint2*)hD, (float4*)out);
}

// round 12
// speedup vs baseline: 1.0267x; 1.0267x over previous
#include <cuda_runtime.h>
#include <cuda_fp16.h>
#include <math.h>

#define NN 50000
#define EE 600000
#define DD 128
#define ELLS 96                    // ELL row stride (max supported degree)

// ---------------- scratch (device globals; no allocation allowed) ----------
__device__ float g_deg[NN];
__device__ float g_dinv[NN];
__device__ int   g_cnt[NN];          // per-dst fill cursor / final count
__device__ uint2 g_cell[NN * ELLS];  // ELL slot: (src index, normalized weight bits)
__device__ unsigned g_h16[NN * 64];  // raw messages h as half2 pairs
__device__ float g_agg[NN * DD];     // aggregated features (layer-0 output, f32)
__device__ float g_sc[2 * DD];       // folded BN scale per layer
__device__ float g_sh[2 * DD];       // folded BN shift (incl. bias) per layer
__device__ float g_alpha;            // sigmoid(act_params[0])

// ---------------- prep kernels (side stream) --------------------------------
__global__ void k_zero() {
    int i = blockIdx.x * blockDim.x + threadIdx.x;
    if (i < NN) {
        g_cnt[i] = 0;
        g_deg[i] = 0.f;
    }
}

// pass 1: weighted degree; 4 independent edges per thread (MLP)
__global__ void k_deg(const int* __restrict__ dst, const float* __restrict__ ew) {
    int t = blockIdx.x * blockDim.x + threadIdx.x;
    int stride = gridDim.x * blockDim.x;
    int   dd[4];
    float ww[4];
    bool  vv[4];
#pragma unroll
    for (int i = 0; i < 4; i++) {
        int e = t + i * stride;
        vv[i] = (e < EE);
        if (vv[i]) {
            dd[i] = dst[e];
            ww[i] = ew[e];
        }
    }
#pragma unroll
    for (int i = 0; i < 4; i++)
        if (vv[i]) atomicAdd(&g_deg[dd[i]], ww[i]);
}

__global__ void k_dinvE() {
    int i = blockIdx.x * blockDim.x + threadIdx.x;
    if (i < NN) g_dinv[i] = rsqrtf(g_deg[i] + 1.0f);  // +1 = self-loop weight
}

// pass 2: ELL fill with fully-normalized weight; 4 edges per thread (MLP)
__global__ void k_fillnorm(const int* __restrict__ src, const int* __restrict__ dst,
                           const float* __restrict__ ew) {
    int t = blockIdx.x * blockDim.x + threadIdx.x;
    int stride = gridDim.x * blockDim.x;
    int   dd[4], ss[4];
    float ww[4];
    bool  vv[4];
#pragma unroll
    for (int i = 0; i < 4; i++) {
        int e = t + i * stride;
        vv[i] = (e < EE);
        if (vv[i]) {
            dd[i] = dst[e];
            ss[i] = src[e];
            ww[i] = ew[e];
        }
    }
    float nw[4];
#pragma unroll
    for (int i = 0; i < 4; i++)
        if (vv[i]) nw[i] = __ldg(&g_dinv[ss[i]]) * ww[i] * __ldg(&g_dinv[dd[i]]);
#pragma unroll
    for (int i = 0; i < 4; i++) {
        if (vv[i]) {
            int c = atomicAdd(&g_cnt[dd[i]], 1);
            if (c < ELLS)
                g_cell[dd[i] * ELLS + c] = make_uint2((unsigned)ss[i],
                                                      __float_as_uint(nw[i]));
        }
    }
}

__global__ void k_bnprep(const float* __restrict__ b0, const float* __restrict__ ga0,
                         const float* __restrict__ be0, const float* __restrict__ m0,
                         const float* __restrict__ v0,
                         const float* __restrict__ b1, const float* __restrict__ ga1,
                         const float* __restrict__ be1, const float* __restrict__ m1,
                         const float* __restrict__ v1,
                         const float* __restrict__ act) {
    int t = threadIdx.x;
    if (t < DD) {
        float sc = ga0[t] * rsqrtf(v0[t] + 1e-5f);
        g_sc[t] = sc;
        g_sh[t] = be0[t] + (b0[t] - m0[t]) * sc;
    } else if (t < 2 * DD) {
        int c = t - DD;
        float sc = ga1[c] * rsqrtf(v1[c] + 1e-5f);
        g_sc[t] = sc;
        g_sh[t] = be1[c] + (b1[c] - m1[c]) * sc;
    }
    if (t == 0) g_alpha = 1.0f / (1.0f + expf(-act[0]));
}

// ---------------- tf32 tensor-core GEMM -------------------------------------
// H16 = A' @ W   (raw fp16 messages; graph-independent)
// A' = A (PRE_POST=0) or adaptive-act(BN0(A)) applied during staging.
#define SMS 132                                    // smem row stride (floats)
#define GEMM_SMEM ((64 * SMS + 128 * SMS) * 4)     // As + Ws

__device__ __forceinline__ unsigned f2tf32(float f) {
    unsigned u;
    asm("cvt.rna.tf32.f32 %0, %1;" : "=r"(u) : "f"(f));
    return u;
}

template <int PRE_POST>
__global__ __launch_bounds__(256) void k_gemm(const float* __restrict__ A,
                                              const float* __restrict__ W,
                                              unsigned* __restrict__ H16, int n) {
    extern __shared__ unsigned sm[];
    unsigned* As = sm;              // [64][SMS]
    unsigned* Ws = sm + 64 * SMS;   // [128][SMS]

    int tid = threadIdx.x;
    int row0 = blockIdx.x * 64;

    // ---- stage W (tf32-converted) ----
    const float4* W4 = (const float4*)W;
#pragma unroll
    for (int i = 0; i < 16; i++) {
        int idx = tid + i * 256;        // 4096 float4 = 128 rows x 32
        int r = idx >> 5, c = idx & 31;
        float4 v = W4[idx];
        uint4 u = make_uint4(f2tf32(v.x), f2tf32(v.y), f2tf32(v.z), f2tf32(v.w));
        *(uint4*)&Ws[r * SMS + c * 4] = u;
    }

    // ---- stage A tile (+ fused BN0 + adaptive act for layer 1), tf32 ----
    float alpha = g_alpha;
    const float4* A4 = (const float4*)A;
#pragma unroll
    for (int i = 0; i < 8; i++) {
        int idx = tid + i * 256;        // 2048 float4 = 64 rows x 32
        int r = idx >> 5, c = idx & 31;
        float4 v = make_float4(0.f, 0.f, 0.f, 0.f);
        if (row0 + r < n) v = A4[(size_t)(row0 + r) * 32 + c];
        if (PRE_POST) {
            float* pv = (float*)&v;
#pragma unroll
            for (int j = 0; j < 4; j++) {
                float t = pv[j] * g_sc[c * 4 + j] + g_sh[c * 4 + j];
                float relu = fmaxf(t, 0.f);
                float gelu = 0.5f * t * (1.f + erff(t * 0.70710678118654752f));
                pv[j] = alpha * relu + (1.f - alpha) * gelu;
            }
        }
        uint4 u = make_uint4(f2tf32(v.x), f2tf32(v.y), f2tf32(v.z), f2tf32(v.w));
        *(uint4*)&As[r * SMS + c * 4] = u;
    }
    __syncthreads();

    int wid = tid >> 5;
    int lane = tid & 31;
    int rw = (wid & 3) * 16;       // row band within tile
    int cw = (wid >> 2) * 64;      // col half
    int q = lane >> 2;             // 0..7
    int m = lane & 3;              // 0..3

    float acc[8][4];
#pragma unroll
    for (int nt = 0; nt < 8; nt++)
#pragma unroll
        for (int j = 0; j < 4; j++) acc[nt][j] = 0.f;

#pragma unroll
    for (int kt = 0; kt < 16; kt++) {
        int k0 = kt * 8;
        const unsigned* Ar = &As[(rw + q) * SMS + k0 + m];
        unsigned a0 = Ar[0];
        unsigned a2 = Ar[4];
        unsigned a1 = Ar[8 * SMS];
        unsigned a3 = Ar[8 * SMS + 4];
#pragma unroll
        for (int nt = 0; nt < 8; nt++) {
            int n0 = cw + nt * 8;
            unsigned b0 = Ws[(k0 + m) * SMS + n0 + q];
            unsigned b1 = Ws[(k0 + m + 4) * SMS + n0 + q];
            asm("mma.sync.aligned.m16n8k8.row.col.f32.tf32.tf32.f32 "
                "{%0,%1,%2,%3}, {%4,%5,%6,%7}, {%8,%9}, {%0,%1,%2,%3};"
                : "+f"(acc[nt][0]), "+f"(acc[nt][1]), "+f"(acc[nt][2]), "+f"(acc[nt][3])
                : "r"(a0), "r"(a1), "r"(a2), "r"(a3), "r"(b0), "r"(b1));
        }
    }

    // ---- epilogue: store raw fp16 message pairs ----
    int r_lo = row0 + rw + q;       // rows r_lo and r_lo+8
#pragma unroll
    for (int nt = 0; nt < 8; nt++) {
        int col = cw + nt * 8 + 2 * m;
        if (r_lo < n) {
            __half2 hv = __floats2half2_rn(acc[nt][0], acc[nt][1]);
            H16[(size_t)r_lo * 64 + (col >> 1)] = *(unsigned*)&hv;
        }
        if (r_lo + 8 < n) {
            __half2 hv = __floats2half2_rn(acc[nt][2], acc[nt][3]);
            H16[(size_t)(r_lo + 8) * 64 + (col >> 1)] = *(unsigned*)&hv;
        }
    }
}

// ---------------- gather: one warp per destination node --------------------
// acc = dinv^2 * m[node] + sum_j w_j * m[src_j]   (w fully normalized in cell)
// POST: apply BN1 before store.
template <int POST>
__global__ __launch_bounds__(256) void k_gather(const uint2* __restrict__ h,
                                                float4* __restrict__ out) {
    int t = blockIdx.x * blockDim.x + threadIdx.x;
    int node = t >> 5;
    int lane = t & 31;
    if (node >= NN) return;

    int beg = node * ELLS;
    int cnt = g_cnt[node];
    if (cnt > ELLS) cnt = ELLS;
    int end = beg + cnt;

    float d = g_dinv[node];
    d *= d;
    uint2 sr = h[(size_t)node * 32 + lane];
    float2 slo = __half22float2(*(__half2*)&sr.x);
    float2 shi = __half22float2(*(__half2*)&sr.y);
    float4 acc = make_float4(slo.x * d, slo.y * d, shi.x * d, shi.y * d);

    int j = beg;
    for (; j + 3 < end; j += 4) {
        uint2 e0 = __ldg(&g_cell[j]);
        uint2 e1 = __ldg(&g_cell[j + 1]);
        uint2 e2 = __ldg(&g_cell[j + 2]);
        uint2 e3 = __ldg(&g_cell[j + 3]);
        float w0 = __uint_as_float(e0.y);
        float w1 = __uint_as_float(e1.y);
        float w2 = __uint_as_float(e2.y);
        float w3 = __uint_as_float(e3.y);
        uint2 r0 = h[(size_t)e0.x * 32 + lane];
        uint2 r1 = h[(size_t)e1.x * 32 + lane];
        uint2 r2 = h[(size_t)e2.x * 32 + lane];
        uint2 r3 = h[(size_t)e3.x * 32 + lane];
        float2 l0 = __half22float2(*(__half2*)&r0.x), h0 = __half22float2(*(__half2*)&r0.y);
        float2 l1 = __half22float2(*(__half2*)&r1.x), h1 = __half22float2(*(__half2*)&r1.y);
        float2 l2 = __half22float2(*(__half2*)&r2.x), h2 = __half22float2(*(__half2*)&r2.y);
        float2 l3 = __half22float2(*(__half2*)&r3.x), h3 = __half22float2(*(__half2*)&r3.y);
        acc.x += w0 * l0.x + w1 * l1.x + w2 * l2.x + w3 * l3.x;
        acc.y += w0 * l0.y + w1 * l1.y + w2 * l2.y + w3 * l3.y;
        acc.z += w0 * h0.x + w1 * h1.x + w2 * h2.x + w3 * h3.x;
        acc.w += w0 * h0.y + w1 * h1.y + w2 * h2.y + w3 * h3.y;
    }
    for (; j < end; j++) {
        uint2 e = __ldg(&g_cell[j]);
        float w = __uint_as_float(e.y);
        uint2 r = h[(size_t)e.x * 32 + lane];
        float2 lo = __half22float2(*(__half2*)&r.x);
        float2 hi = __half22float2(*(__half2*)&r.y);
        acc.x += w * lo.x;
        acc.y += w * lo.y;
        acc.z += w * hi.x;
        acc.w += w * hi.y;
    }

    if (POST) {
        int c0 = lane * 4 + DD;   // layer-1 BN params
        acc.x = acc.x * g_sc[c0 + 0] + g_sh[c0 + 0];
        acc.y = acc.y * g_sc[c0 + 1] + g_sh[c0 + 1];
        acc.z = acc.z * g_sc[c0 + 2] + g_sh[c0 + 2];
        acc.w = acc.w * g_sc[c0 + 3] + g_sh[c0 + 3];
    }
    out[(size_t)node * 32 + lane] = acc;
}

// ---------------- launch ----------------------------------------------------
extern "C" void kernel_launch(void* const* d_in, const int* in_sizes, int n_in,
                              void* d_out, int out_size) {
    const float* x  = (const float*)d_in[0];
    const int*   ei = (const int*)d_in[1];     // [2,E]: row0=src, row1=dst
    const float* ew = (const float*)d_in[2];
    const float* W0 = (const float*)d_in[3];
    const float* b0 = (const float*)d_in[4];
    const float* W1 = (const float*)d_in[5];
    const float* b1 = (const float*)d_in[6];
    const float* ga0 = (const float*)d_in[7];
    const float* be0 = (const float*)d_in[8];
    const float* m0  = (const float*)d_in[9];
    const float* v0  = (const float*)d_in[10];
    const float* ga1 = (const float*)d_in[11];
    const float* be1 = (const float*)d_in[12];
    const float* m1  = (const float*)d_in[13];
    const float* v1  = (const float*)d_in[14];
    const float* act = (const float*)d_in[15];
    float* out = (float*)d_out;

    const int* src = ei;
    const int* dst = ei + EE;

    unsigned* hD; cudaGetSymbolAddress((void**)&hD, g_h16);
    float* aggD;  cudaGetSymbolAddress((void**)&aggD, g_agg);

    cudaFuncSetAttribute(k_gemm<0>, cudaFuncAttributeMaxDynamicSharedMemorySize, GEMM_SMEM);
    cudaFuncSetAttribute(k_gemm<1>, cudaFuncAttributeMaxDynamicSharedMemorySize, GEMM_SMEM);

    // side stream + fork/join events (created once; capture-safe fork pattern)
    static cudaStream_t sA = nullptr;
    static cudaEvent_t evFork = nullptr, evJoin = nullptr;
    if (sA == nullptr) {
        cudaStreamCreateWithFlags(&sA, cudaStreamNonBlocking);
        cudaEventCreateWithFlags(&evFork, cudaEventDisableTiming);
        cudaEventCreateWithFlags(&evJoin, cudaEventDisableTiming);
    }

    const int B = 256;
    int gN    = (NN + B - 1) / B;
    int gE4   = (EE + 4 * B - 1) / (4 * B);
    int gGth  = (NN * 32 + B - 1) / B;
    int gGemm = (NN + 63) / 64;

    // ---- fork: graph prep on side stream, concurrent with layer-0 GEMM ----
    cudaEventRecord(evFork, 0);
    cudaStreamWaitEvent(sA, evFork, 0);
    k_zero<<<gN, B, 0, sA>>>();
    k_deg<<<gE4, B, 0, sA>>>(dst, ew);
    k_dinvE<<<gN, B, 0, sA>>>();
    k_fillnorm<<<gE4, B, 0, sA>>>(src, dst, ew);
    cudaEventRecord(evJoin, sA);

    // ---- main stream: layer-0 GEMM (graph-independent), then bn prep ----
    k_gemm<0><<<gGemm, B, GEMM_SMEM>>>(x, W0, hD, NN);
    k_bnprep<<<1, 256>>>(b0, ga0, be0, m0, v0, b1, ga1, be1, m1, v1, act);

    // ---- join: gather needs ELL + dinv ----
    cudaStreamWaitEvent(0, evJoin, 0);
    k_gather<0><<<gGth, B>>>((const uint2*)hD, (float4*)aggD);

    // layer 1
    k_gemm<1><<<gGemm, B, GEMM_SMEM>>>(aggD, W1, hD, NN);
    k_gather<1><<<gGth, B>>>((const uint2*)hD, (float4*)out);
}

// round 13
// speedup vs baseline: 1.1217x; 1.0925x over previous
#include <cuda_runtime.h>
#include <cuda_fp16.h>
#include <math.h>

#define NN 50000
#define EE 600000
#define DD 128
#define ELLS 96                    // ELL row stride (max supported degree)

// ---------------- scratch (device globals; no allocation allowed) ----------
__device__ float g_deg[NN];
__device__ float g_dinv[NN];
__device__ int   g_cnt[NN];          // per-dst fill cursor / final count
__device__ uint2 g_cell[NN * ELLS];  // ELL slot: (src index, weight bits)
__device__ unsigned g_h16[NN * 64];  // raw messages h as half2 pairs
__device__ float g_agg[NN * DD];     // aggregated features (layer-0 output, f32)
__device__ float g_sc[2 * DD];       // folded BN scale per layer
__device__ float g_sh[2 * DD];       // folded BN shift (incl. bias) per layer
__device__ float g_alpha;            // sigmoid(act_params[0])

// ---------------- prep kernels ----------------------------------------------
__global__ void k_zero() {
    int i = blockIdx.x * blockDim.x + threadIdx.x;
    if (i < NN) {
        g_cnt[i] = 0;
        g_deg[i] = 0.f;
    }
}

// single edge pass: weighted degree + ELL fill (raw weight); ILP2
__global__ void k_degfill(const int* __restrict__ src, const int* __restrict__ dst,
                          const float* __restrict__ ew) {
    int t = blockIdx.x * blockDim.x + threadIdx.x;
    int stride = gridDim.x * blockDim.x;
    int   dd[2], ss[2];
    float ww[2];
    bool  vv[2];
#pragma unroll
    for (int i = 0; i < 2; i++) {
        int e = t + i * stride;
        vv[i] = (e < EE);
        if (vv[i]) {
            dd[i] = dst[e];
            ss[i] = src[e];
            ww[i] = ew[e];
        }
    }
#pragma unroll
    for (int i = 0; i < 2; i++) {
        if (vv[i]) {
            atomicAdd(&g_deg[dd[i]], ww[i]);
            int c = atomicAdd(&g_cnt[dd[i]], 1);
            if (c < ELLS)
                g_cell[dd[i] * ELLS + c] = make_uint2((unsigned)ss[i],
                                                      __float_as_uint(ww[i]));
        }
    }
}

// fused: dinv compute + store, and in-place slot normalization
// w = ew * rsqrt(deg[d]+1) * rsqrt(deg[s]+1)
__global__ void k_wnormF() {
    int t = blockIdx.x * blockDim.x + threadIdx.x;
    int node = t >> 5;
    int lane = t & 31;
    if (node >= NN) return;
    float dn = rsqrtf(g_deg[node] + 1.0f);   // +1 = self-loop weight
    if (lane == 0) g_dinv[node] = dn;
    int cnt = g_cnt[node];
    if (cnt > ELLS) cnt = ELLS;
    int beg = node * ELLS;
    for (int j = lane; j < cnt; j += 32) {
        uint2 cell = g_cell[beg + j];
        float w = __uint_as_float(cell.y) * dn *
                  rsqrtf(__ldg(&g_deg[cell.x]) + 1.0f);
        g_cell[beg + j].y = __float_as_uint(w);
    }
}

__global__ void k_bnprep(const float* __restrict__ b0, const float* __restrict__ ga0,
                         const float* __restrict__ be0, const float* __restrict__ m0,
                         const float* __restrict__ v0,
                         const float* __restrict__ b1, const float* __restrict__ ga1,
                         const float* __restrict__ be1, const float* __restrict__ m1,
                         const float* __restrict__ v1,
                         const float* __restrict__ act) {
    int t = threadIdx.x;
    if (t < DD) {
        float sc = ga0[t] * rsqrtf(v0[t] + 1e-5f);
        g_sc[t] = sc;
        g_sh[t] = be0[t] + (b0[t] - m0[t]) * sc;
    } else if (t < 2 * DD) {
        int c = t - DD;
        float sc = ga1[c] * rsqrtf(v1[c] + 1e-5f);
        g_sc[t] = sc;
        g_sh[t] = be1[c] + (b1[c] - m1[c]) * sc;
    }
    if (t == 0) g_alpha = 1.0f / (1.0f + expf(-act[0]));
}

// ---------------- tf32 tensor-core GEMM -------------------------------------
// H16 = A' @ W   (raw fp16 messages; graph-independent)
// A' = A (PRE_POST=0) or adaptive-act(BN0(A)) applied during staging.
#define SMS 132                                    // smem row stride (floats)
#define GEMM_SMEM ((64 * SMS + 128 * SMS) * 4)     // As + Ws

__device__ __forceinline__ unsigned f2tf32(float f) {
    unsigned u;
    asm("cvt.rna.tf32.f32 %0, %1;" : "=r"(u) : "f"(f));
    return u;
}

template <int PRE_POST>
__global__ __launch_bounds__(256) void k_gemm(const float* __restrict__ A,
                                              const float* __restrict__ W,
                                              unsigned* __restrict__ H16, int n) {
    extern __shared__ unsigned sm[];
    unsigned* As = sm;              // [64][SMS]
    unsigned* Ws = sm + 64 * SMS;   // [128][SMS]

    int tid = threadIdx.x;
    int row0 = blockIdx.x * 64;

    // ---- stage W (tf32-converted) ----
    const float4* W4 = (const float4*)W;
#pragma unroll
    for (int i = 0; i < 16; i++) {
        int idx = tid + i * 256;        // 4096 float4 = 128 rows x 32
        int r = idx >> 5, c = idx & 31;
        float4 v = W4[idx];
        uint4 u = make_uint4(f2tf32(v.x), f2tf32(v.y), f2tf32(v.z), f2tf32(v.w));
        *(uint4*)&Ws[r * SMS + c * 4] = u;
    }

    // ---- stage A tile (+ fused BN0 + adaptive act for layer 1), tf32 ----
    float alpha = g_alpha;
    const float4* A4 = (const float4*)A;
#pragma unroll
    for (int i = 0; i < 8; i++) {
        int idx = tid + i * 256;        // 2048 float4 = 64 rows x 32
        int r = idx >> 5, c = idx & 31;
        float4 v = make_float4(0.f, 0.f, 0.f, 0.f);
        if (row0 + r < n) v = A4[(size_t)(row0 + r) * 32 + c];
        if (PRE_POST) {
            float* pv = (float*)&v;
#pragma unroll
            for (int j = 0; j < 4; j++) {
                float t = pv[j] * g_sc[c * 4 + j] + g_sh[c * 4 + j];
                float relu = fmaxf(t, 0.f);
                float gelu = 0.5f * t * (1.f + erff(t * 0.70710678118654752f));
                pv[j] = alpha * relu + (1.f - alpha) * gelu;
            }
        }
        uint4 u = make_uint4(f2tf32(v.x), f2tf32(v.y), f2tf32(v.z), f2tf32(v.w));
        *(uint4*)&As[r * SMS + c * 4] = u;
    }
    __syncthreads();

    int wid = tid >> 5;
    int lane = tid & 31;
    int rw = (wid & 3) * 16;       // row band within tile
    int cw = (wid >> 2) * 64;      // col half
    int q = lane >> 2;             // 0..7
    int m = lane & 3;              // 0..3

    float acc[8][4];
#pragma unroll
    for (int nt = 0; nt < 8; nt++)
#pragma unroll
        for (int j = 0; j < 4; j++) acc[nt][j] = 0.f;

#pragma unroll
    for (int kt = 0; kt < 16; kt++) {
        int k0 = kt * 8;
        const unsigned* Ar = &As[(rw + q) * SMS + k0 + m];
        unsigned a0 = Ar[0];
        unsigned a2 = Ar[4];
        unsigned a1 = Ar[8 * SMS];
        unsigned a3 = Ar[8 * SMS + 4];
#pragma unroll
        for (int nt = 0; nt < 8; nt++) {
            int n0 = cw + nt * 8;
            unsigned b0 = Ws[(k0 + m) * SMS + n0 + q];
            unsigned b1 = Ws[(k0 + m + 4) * SMS + n0 + q];
            asm("mma.sync.aligned.m16n8k8.row.col.f32.tf32.tf32.f32 "
                "{%0,%1,%2,%3}, {%4,%5,%6,%7}, {%8,%9}, {%0,%1,%2,%3};"
                : "+f"(acc[nt][0]), "+f"(acc[nt][1]), "+f"(acc[nt][2]), "+f"(acc[nt][3])
                : "r"(a0), "r"(a1), "r"(a2), "r"(a3), "r"(b0), "r"(b1));
        }
    }

    // ---- epilogue: store raw fp16 message pairs ----
    int r_lo = row0 + rw + q;       // rows r_lo and r_lo+8
#pragma unroll
    for (int nt = 0; nt < 8; nt++) {
        int col = cw + nt * 8 + 2 * m;
        if (r_lo < n) {
            __half2 hv = __floats2half2_rn(acc[nt][0], acc[nt][1]);
            H16[(size_t)r_lo * 64 + (col >> 1)] = *(unsigned*)&hv;
        }
        if (r_lo + 8 < n) {
            __half2 hv = __floats2half2_rn(acc[nt][2], acc[nt][3]);
            H16[(size_t)(r_lo + 8) * 64 + (col >> 1)] = *(unsigned*)&hv;
        }
    }
}

// ---------------- gather: one warp per destination node --------------------
// acc = dinv^2 * m[node] + sum_j w_j * m[src_j]   (w fully normalized in cell)
// POST: apply BN1 before store.
template <int POST>
__global__ __launch_bounds__(256) void k_gather(const uint2* __restrict__ h,
                                                float4* __restrict__ out) {
    int t = blockIdx.x * blockDim.x + threadIdx.x;
    int node = t >> 5;
    int lane = t & 31;
    if (node >= NN) return;

    int beg = node * ELLS;
    int cnt = g_cnt[node];
    if (cnt > ELLS) cnt = ELLS;
    int end = beg + cnt;

    float d = g_dinv[node];
    d *= d;
    uint2 sr = h[(size_t)node * 32 + lane];
    float2 slo = __half22float2(*(__half2*)&sr.x);
    float2 shi = __half22float2(*(__half2*)&sr.y);
    float4 acc = make_float4(slo.x * d, slo.y * d, shi.x * d, shi.y * d);

    int j = beg;
    for (; j + 3 < end; j += 4) {
        uint2 e0 = __ldg(&g_cell[j]);
        uint2 e1 = __ldg(&g_cell[j + 1]);
        uint2 e2 = __ldg(&g_cell[j + 2]);
        uint2 e3 = __ldg(&g_cell[j + 3]);
        float w0 = __uint_as_float(e0.y);
        float w1 = __uint_as_float(e1.y);
        float w2 = __uint_as_float(e2.y);
        float w3 = __uint_as_float(e3.y);
        uint2 r0 = h[(size_t)e0.x * 32 + lane];
        uint2 r1 = h[(size_t)e1.x * 32 + lane];
        uint2 r2 = h[(size_t)e2.x * 32 + lane];
        uint2 r3 = h[(size_t)e3.x * 32 + lane];
        float2 l0 = __half22float2(*(__half2*)&r0.x), h0 = __half22float2(*(__half2*)&r0.y);
        float2 l1 = __half22float2(*(__half2*)&r1.x), h1 = __half22float2(*(__half2*)&r1.y);
        float2 l2 = __half22float2(*(__half2*)&r2.x), h2 = __half22float2(*(__half2*)&r2.y);
        float2 l3 = __half22float2(*(__half2*)&r3.x), h3 = __half22float2(*(__half2*)&r3.y);
        acc.x += w0 * l0.x + w1 * l1.x + w2 * l2.x + w3 * l3.x;
        acc.y += w0 * l0.y + w1 * l1.y + w2 * l2.y + w3 * l3.y;
        acc.z += w0 * h0.x + w1 * h1.x + w2 * h2.x + w3 * h3.x;
        acc.w += w0 * h0.y + w1 * h1.y + w2 * h2.y + w3 * h3.y;
    }
    for (; j < end; j++) {
        uint2 e = __ldg(&g_cell[j]);
        float w = __uint_as_float(e.y);
        uint2 r = h[(size_t)e.x * 32 + lane];
        float2 lo = __half22float2(*(__half2*)&r.x);
        float2 hi = __half22float2(*(__half2*)&r.y);
        acc.x += w * lo.x;
        acc.y += w * lo.y;
        acc.z += w * hi.x;
        acc.w += w * hi.y;
    }

    if (POST) {
        int c0 = lane * 4 + DD;   // layer-1 BN params
        acc.x = acc.x * g_sc[c0 + 0] + g_sh[c0 + 0];
        acc.y = acc.y * g_sc[c0 + 1] + g_sh[c0 + 1];
        acc.z = acc.z * g_sc[c0 + 2] + g_sh[c0 + 2];
        acc.w = acc.w * g_sc[c0 + 3] + g_sh[c0 + 3];
    }
    out[(size_t)node * 32 + lane] = acc;
}

// ---------------- launch ----------------------------------------------------
extern "C" void kernel_launch(void* const* d_in, const int* in_sizes, int n_in,
                              void* d_out, int out_size) {
    const float* x  = (const float*)d_in[0];
    const int*   ei = (const int*)d_in[1];     // [2,E]: row0=src, row1=dst
    const float* ew = (const float*)d_in[2];
    const float* W0 = (const float*)d_in[3];
    const float* b0 = (const float*)d_in[4];
    const float* W1 = (const float*)d_in[5];
    const float* b1 = (const float*)d_in[6];
    const float* ga0 = (const float*)d_in[7];
    const float* be0 = (const float*)d_in[8];
    const float* m0  = (const float*)d_in[9];
    const float* v0  = (const float*)d_in[10];
    const float* ga1 = (const float*)d_in[11];
    const float* be1 = (const float*)d_in[12];
    const float* m1  = (const float*)d_in[13];
    const float* v1  = (const float*)d_in[14];
    const float* act = (const float*)d_in[15];
    float* out = (float*)d_out;

    const int* src = ei;
    const int* dst = ei + EE;

    unsigned* hD; cudaGetSymbolAddress((void**)&hD, g_h16);
    float* aggD;  cudaGetSymbolAddress((void**)&aggD, g_agg);

    cudaFuncSetAttribute(k_gemm<0>, cudaFuncAttributeMaxDynamicSharedMemorySize, GEMM_SMEM);
    cudaFuncSetAttribute(k_gemm<1>, cudaFuncAttributeMaxDynamicSharedMemorySize, GEMM_SMEM);

    // side stream + fork/join events (created once; capture-safe fork pattern)
    static cudaStream_t sA = nullptr;
    static cudaEvent_t evFork = nullptr, evJoin = nullptr;
    if (sA == nullptr) {
        cudaStreamCreateWithFlags(&sA, cudaStreamNonBlocking);
        cudaEventCreateWithFlags(&evFork, cudaEventDisableTiming);
        cudaEventCreateWithFlags(&evJoin, cudaEventDisableTiming);
    }

    const int B = 256;
    int gN    = (NN + B - 1) / B;
    int gE2   = (EE + 2 * B - 1) / (2 * B);
    int gGth  = (NN * 32 + B - 1) / B;
    int gGemm = (NN + 63) / 64;

    // ---- main stream: zero first (both streams depend on it) ----
    k_zero<<<gN, B>>>();

    // ---- fork: graph prep on side stream, concurrent with layer-0 GEMM ----
    cudaEventRecord(evFork, 0);
    cudaStreamWaitEvent(sA, evFork, 0);
    k_degfill<<<gE2, B, 0, sA>>>(src, dst, ew);
    k_wnormF<<<gGth, B, 0, sA>>>();
    cudaEventRecord(evJoin, sA);

    // ---- main stream: layer-0 GEMM (graph-independent), then bn prep ----
    k_gemm<0><<<gGemm, B, GEMM_SMEM>>>(x, W0, hD, NN);
    k_bnprep<<<1, 256>>>(b0, ga0, be0, m0, v0, b1, ga1, be1, m1, v1, act);

    // ---- join: gather needs ELL + dinv ----
    cudaStreamWaitEvent(0, evJoin, 0);
    k_gather<0><<<gGth, B>>>((const uint2*)hD, (float4*)aggD);

    // layer 1
    k_gemm<1><<<gGemm, B, GEMM_SMEM>>>(aggD, W1, hD, NN);
    k_gather<1><<<gGth, B>>>((const uint2*)hD, (float4*)out);
}

// round 14
// speedup vs baseline: 1.2880x; 1.1483x over previous
#include <cuda_runtime.h>
#include <cuda_fp16.h>
#include <math.h>

#define NN 50000
#define EE 600000
#define DD 128
#define ELLS 96                    // ELL row stride (max supported degree)

// ---------------- scratch (device globals; no allocation allowed) ----------
__device__ float g_deg[NN];
__device__ float g_dinv[NN];
__device__ int   g_cnt[NN];          // per-dst fill cursor / final count
__device__ uint2 g_cell[NN * ELLS];  // ELL slot: (src index, weight bits)
__device__ unsigned g_h16[NN * 64];  // raw messages h as half2 pairs
__device__ float g_agg[NN * DD];     // aggregated features (layer-0 output, f32)
__device__ float g_sc[2 * DD];       // folded BN scale per layer
__device__ float g_sh[2 * DD];       // folded BN shift (incl. bias) per layer
__device__ float g_alpha;            // sigmoid(act_params[0])

// ---------------- prep kernels ----------------------------------------------
__global__ void k_zero() {
    int i = blockIdx.x * blockDim.x + threadIdx.x;
    if (i < NN) {
        g_cnt[i] = 0;
        g_deg[i] = 0.f;
    }
}

// single edge pass: weighted degree + ELL fill (raw weight); ILP2
__global__ void k_degfill(const int* __restrict__ src, const int* __restrict__ dst,
                          const float* __restrict__ ew) {
    int t = blockIdx.x * blockDim.x + threadIdx.x;
    int stride = gridDim.x * blockDim.x;
    int   dd[2], ss[2];
    float ww[2];
    bool  vv[2];
#pragma unroll
    for (int i = 0; i < 2; i++) {
        int e = t + i * stride;
        vv[i] = (e < EE);
        if (vv[i]) {
            dd[i] = dst[e];
            ss[i] = src[e];
            ww[i] = ew[e];
        }
    }
#pragma unroll
    for (int i = 0; i < 2; i++) {
        if (vv[i]) {
            atomicAdd(&g_deg[dd[i]], ww[i]);
            int c = atomicAdd(&g_cnt[dd[i]], 1);
            if (c < ELLS)
                g_cell[dd[i] * ELLS + c] = make_uint2((unsigned)ss[i],
                                                      __float_as_uint(ww[i]));
        }
    }
}

// fused: dinv compute + store, and in-place slot normalization
__global__ void k_wnormF() {
    int t = blockIdx.x * blockDim.x + threadIdx.x;
    int node = t >> 5;
    int lane = t & 31;
    if (node >= NN) return;
    float dn = rsqrtf(g_deg[node] + 1.0f);   // +1 = self-loop weight
    if (lane == 0) g_dinv[node] = dn;
    int cnt = g_cnt[node];
    if (cnt > ELLS) cnt = ELLS;
    int beg = node * ELLS;
    for (int j = lane; j < cnt; j += 32) {
        uint2 cell = g_cell[beg + j];
        float w = __uint_as_float(cell.y) * dn *
                  rsqrtf(__ldg(&g_deg[cell.x]) + 1.0f);
        g_cell[beg + j].y = __float_as_uint(w);
    }
}

__global__ void k_bnprep(const float* __restrict__ b0, const float* __restrict__ ga0,
                         const float* __restrict__ be0, const float* __restrict__ m0,
                         const float* __restrict__ v0,
                         const float* __restrict__ b1, const float* __restrict__ ga1,
                         const float* __restrict__ be1, const float* __restrict__ m1,
                         const float* __restrict__ v1,
                         const float* __restrict__ act) {
    int t = threadIdx.x;
    if (t < DD) {
        float sc = ga0[t] * rsqrtf(v0[t] + 1e-5f);
        g_sc[t] = sc;
        g_sh[t] = be0[t] + (b0[t] - m0[t]) * sc;
    } else if (t < 2 * DD) {
        int c = t - DD;
        float sc = ga1[c] * rsqrtf(v1[c] + 1e-5f);
        g_sc[t] = sc;
        g_sh[t] = be1[c] + (b1[c] - m1[c]) * sc;
    }
    if (t == 0) g_alpha = 1.0f / (1.0f + expf(-act[0]));
}

// ---------------- fp16 tensor-core GEMM -------------------------------------
// H16 = A' @ W with fp16 inputs, fp32 accumulate (mma.m16n8k16).
// A' = A (PRE_POST=0) or adaptive-act(BN0(A)) applied during staging.
// SMEM (words of 4B): As[64][68] (half pairs), WsT[128][68] transposed W.
#define SMSW 68                                    // smem row stride (32-bit words)
#define GEMM_SMEM ((64 * SMSW + 128 * SMSW) * 4)   // 52.2 KB -> 4 blocks/SM

template <int PRE_POST>
__global__ __launch_bounds__(256, 4) void k_gemm(const float* __restrict__ A,
                                                 const float* __restrict__ W,
                                                 unsigned* __restrict__ H16, int n) {
    extern __shared__ unsigned sm[];
    unsigned* As  = sm;               // [64][SMSW]  A rows (k halves packed)
    unsigned* WsT = sm + 64 * SMSW;   // [128][SMSW] W^T: row n, k halves packed

    int tid = threadIdx.x;
    int row0 = blockIdx.x * 64;

    // ---- stage W transposed as half: WsT[n][k] ----
    const float4* W4 = (const float4*)W;
#pragma unroll
    for (int it = 0; it < 4; it++) {
        int task = tid + it * 256;      // 1024 tasks = 32 Rg x 32 Cg
        int Rg = task >> 5;             // k rows 4Rg..4Rg+3
        int Cg = task & 31;             // n cols 4Cg..4Cg+3
        float4 v0 = W4[(4 * Rg + 0) * 32 + Cg];
        float4 v1 = W4[(4 * Rg + 1) * 32 + Cg];
        float4 v2 = W4[(4 * Rg + 2) * 32 + Cg];
        float4 v3 = W4[(4 * Rg + 3) * 32 + Cg];
        const float* p0 = (const float*)&v0;
        const float* p1 = (const float*)&v1;
        const float* p2 = (const float*)&v2;
        const float* p3 = (const float*)&v3;
#pragma unroll
        for (int i = 0; i < 4; i++) {
            __half2 lo = __floats2half2_rn(p0[i], p1[i]);   // k = 4Rg, 4Rg+1
            __half2 hi = __floats2half2_rn(p2[i], p3[i]);   // k = 4Rg+2, 4Rg+3
            int base = (4 * Cg + i) * SMSW + 2 * Rg;
            WsT[base]     = *(unsigned*)&lo;
            WsT[base + 1] = *(unsigned*)&hi;
        }
    }

    // ---- stage A tile as half (+ fused BN0 + adaptive act for layer 1) ----
    float alpha = g_alpha;
    const float4* A4 = (const float4*)A;
#pragma unroll
    for (int i = 0; i < 8; i++) {
        int idx = tid + i * 256;        // 2048 float4 = 64 rows x 32
        int r = idx >> 5, c = idx & 31;
        float4 v = make_float4(0.f, 0.f, 0.f, 0.f);
        if (row0 + r < n) v = A4[(size_t)(row0 + r) * 32 + c];
        if (PRE_POST) {
            float* pv = (float*)&v;
#pragma unroll
            for (int j = 0; j < 4; j++) {
                float t = pv[j] * g_sc[c * 4 + j] + g_sh[c * 4 + j];
                float relu = fmaxf(t, 0.f);
                float gelu = 0.5f * t * (1.f + erff(t * 0.70710678118654752f));
                pv[j] = alpha * relu + (1.f - alpha) * gelu;
            }
        }
        __half2 h01 = __floats2half2_rn(v.x, v.y);
        __half2 h23 = __floats2half2_rn(v.z, v.w);
        uint2 pack = make_uint2(*(unsigned*)&h01, *(unsigned*)&h23);
        *(uint2*)&As[r * SMSW + 2 * c] = pack;
    }
    __syncthreads();

    int wid = tid >> 5;
    int lane = tid & 31;
    int rw = (wid & 3) * 16;       // row band within tile
    int cw = (wid >> 2) * 64;      // col half
    int q = lane >> 2;             // 0..7
    int m = lane & 3;              // 0..3

    float acc[8][4];
#pragma unroll
    for (int nt = 0; nt < 8; nt++)
#pragma unroll
        for (int j = 0; j < 4; j++) acc[nt][j] = 0.f;

#pragma unroll
    for (int kt = 0; kt < 8; kt++) {
        int k0w = kt * 8;               // word offset = 16 halves per kt
        const unsigned* Ar = &As[(rw + q) * SMSW + k0w + m];
        unsigned a0 = Ar[0];            // A[rw+q][k: 2m,2m+1]
        unsigned a2 = Ar[4];            // A[rw+q][k: 2m+8,2m+9]
        unsigned a1 = Ar[8 * SMSW];     // A[rw+q+8][...]
        unsigned a3 = Ar[8 * SMSW + 4];
#pragma unroll
        for (int nt = 0; nt < 8; nt++) {
            int n0 = cw + nt * 8;
            unsigned b0 = WsT[(n0 + q) * SMSW + k0w + m];       // W^T[n][k:2m,2m+1]
            unsigned b1 = WsT[(n0 + q) * SMSW + k0w + m + 4];   // k: 2m+8,2m+9
            asm("mma.sync.aligned.m16n8k16.row.col.f32.f16.f16.f32 "
                "{%0,%1,%2,%3}, {%4,%5,%6,%7}, {%8,%9}, {%0,%1,%2,%3};"
                : "+f"(acc[nt][0]), "+f"(acc[nt][1]), "+f"(acc[nt][2]), "+f"(acc[nt][3])
                : "r"(a0), "r"(a1), "r"(a2), "r"(a3), "r"(b0), "r"(b1));
        }
    }

    // ---- epilogue: store raw fp16 message pairs ----
    int r_lo = row0 + rw + q;       // rows r_lo and r_lo+8
#pragma unroll
    for (int nt = 0; nt < 8; nt++) {
        int col = cw + nt * 8 + 2 * m;
        if (r_lo < n) {
            __half2 hv = __floats2half2_rn(acc[nt][0], acc[nt][1]);
            H16[(size_t)r_lo * 64 + (col >> 1)] = *(unsigned*)&hv;
        }
        if (r_lo + 8 < n) {
            __half2 hv = __floats2half2_rn(acc[nt][2], acc[nt][3]);
            H16[(size_t)(r_lo + 8) * 64 + (col >> 1)] = *(unsigned*)&hv;
        }
    }
}

// ---------------- gather: one warp per destination node --------------------
// acc = dinv^2 * m[node] + sum_j w_j * m[src_j]   (w fully normalized in cell)
// POST: apply BN1 before store.
template <int POST>
__global__ __launch_bounds__(256) void k_gather(const uint2* __restrict__ h,
                                                float4* __restrict__ out) {
    int t = blockIdx.x * blockDim.x + threadIdx.x;
    int node = t >> 5;
    int lane = t & 31;
    if (node >= NN) return;

    int beg = node * ELLS;
    int cnt = g_cnt[node];
    if (cnt > ELLS) cnt = ELLS;
    int end = beg + cnt;

    float d = g_dinv[node];
    d *= d;
    uint2 sr = h[(size_t)node * 32 + lane];
    float2 slo = __half22float2(*(__half2*)&sr.x);
    float2 shi = __half22float2(*(__half2*)&sr.y);
    float4 acc = make_float4(slo.x * d, slo.y * d, shi.x * d, shi.y * d);

    int j = beg;
    for (; j + 3 < end; j += 4) {
        uint2 e0 = __ldg(&g_cell[j]);
        uint2 e1 = __ldg(&g_cell[j + 1]);
        uint2 e2 = __ldg(&g_cell[j + 2]);
        uint2 e3 = __ldg(&g_cell[j + 3]);
        float w0 = __uint_as_float(e0.y);
        float w1 = __uint_as_float(e1.y);
        float w2 = __uint_as_float(e2.y);
        float w3 = __uint_as_float(e3.y);
        uint2 r0 = h[(size_t)e0.x * 32 + lane];
        uint2 r1 = h[(size_t)e1.x * 32 + lane];
        uint2 r2 = h[(size_t)e2.x * 32 + lane];
        uint2 r3 = h[(size_t)e3.x * 32 + lane];
        float2 l0 = __half22float2(*(__half2*)&r0.x), h0 = __half22float2(*(__half2*)&r0.y);
        float2 l1 = __half22float2(*(__half2*)&r1.x), h1 = __half22float2(*(__half2*)&r1.y);
        float2 l2 = __half22float2(*(__half2*)&r2.x), h2 = __half22float2(*(__half2*)&r2.y);
        float2 l3 = __half22float2(*(__half2*)&r3.x), h3 = __half22float2(*(__half2*)&r3.y);
        acc.x += w0 * l0.x + w1 * l1.x + w2 * l2.x + w3 * l3.x;
        acc.y += w0 * l0.y + w1 * l1.y + w2 * l2.y + w3 * l3.y;
        acc.z += w0 * h0.x + w1 * h1.x + w2 * h2.x + w3 * h3.x;
        acc.w += w0 * h0.y + w1 * h1.y + w2 * h2.y + w3 * h3.y;
    }
    for (; j < end; j++) {
        uint2 e = __ldg(&g_cell[j]);
        float w = __uint_as_float(e.y);
        uint2 r = h[(size_t)e.x * 32 + lane];
        float2 lo = __half22float2(*(__half2*)&r.x);
        float2 hi = __half22float2(*(__half2*)&r.y);
        acc.x += w * lo.x;
        acc.y += w * lo.y;
        acc.z += w * hi.x;
        acc.w += w * hi.y;
    }

    if (POST) {
        int c0 = lane * 4 + DD;   // layer-1 BN params
        acc.x = acc.x * g_sc[c0 + 0] + g_sh[c0 + 0];
        acc.y = acc.y * g_sc[c0 + 1] + g_sh[c0 + 1];
        acc.z = acc.z * g_sc[c0 + 2] + g_sh[c0 + 2];
        acc.w = acc.w * g_sc[c0 + 3] + g_sh[c0 + 3];
    }
    out[(size_t)node * 32 + lane] = acc;
}

// ---------------- launch ----------------------------------------------------
extern "C" void kernel_launch(void* const* d_in, const int* in_sizes, int n_in,
                              void* d_out, int out_size) {
    const float* x  = (const float*)d_in[0];
    const int*   ei = (const int*)d_in[1];     // [2,E]: row0=src, row1=dst
    const float* ew = (const float*)d_in[2];
    const float* W0 = (const float*)d_in[3];
    const float* b0 = (const float*)d_in[4];
    const float* W1 = (const float*)d_in[5];
    const float* b1 = (const float*)d_in[6];
    const float* ga0 = (const float*)d_in[7];
    const float* be0 = (const float*)d_in[8];
    const float* m0  = (const float*)d_in[9];
    const float* v0  = (const float*)d_in[10];
    const float* ga1 = (const float*)d_in[11];
    const float* be1 = (const float*)d_in[12];
    const float* m1  = (const float*)d_in[13];
    const float* v1  = (const float*)d_in[14];
    const float* act = (const float*)d_in[15];
    float* out = (float*)d_out;

    const int* src = ei;
    const int* dst = ei + EE;

    unsigned* hD; cudaGetSymbolAddress((void**)&hD, g_h16);
    float* aggD;  cudaGetSymbolAddress((void**)&aggD, g_agg);

    cudaFuncSetAttribute(k_gemm<0>, cudaFuncAttributeMaxDynamicSharedMemorySize, GEMM_SMEM);
    cudaFuncSetAttribute(k_gemm<1>, cudaFuncAttributeMaxDynamicSharedMemorySize, GEMM_SMEM);

    // side stream + fork/join events (created once; capture-safe fork pattern)
    static cudaStream_t sA = nullptr;
    static cudaEvent_t evFork = nullptr, evJoin = nullptr;
    if (sA == nullptr) {
        cudaStreamCreateWithFlags(&sA, cudaStreamNonBlocking);
        cudaEventCreateWithFlags(&evFork, cudaEventDisableTiming);
        cudaEventCreateWithFlags(&evJoin, cudaEventDisableTiming);
    }

    const int B = 256;
    int gN    = (NN + B - 1) / B;
    int gE2   = (EE + 2 * B - 1) / (2 * B);
    int gGth  = (NN * 32 + B - 1) / B;
    int gGemm = (NN + 63) / 64;

    // ---- main stream: zero first (both streams depend on it) ----
    k_zero<<<gN, B>>>();

    // ---- fork: graph prep on side stream, concurrent with layer-0 GEMM ----
    cudaEventRecord(evFork, 0);
    cudaStreamWaitEvent(sA, evFork, 0);
    k_degfill<<<gE2, B, 0, sA>>>(src, dst, ew);
    k_wnormF<<<gGth, B, 0, sA>>>();
    cudaEventRecord(evJoin, sA);

    // ---- main stream: layer-0 GEMM (graph-independent), then bn prep ----
    k_gemm<0><<<gGemm, B, GEMM_SMEM>>>(x, W0, hD, NN);
    k_bnprep<<<1, 256>>>(b0, ga0, be0, m0, v0, b1, ga1, be1, m1, v1, act);

    // ---- join: gather needs ELL + dinv ----
    cudaStreamWaitEvent(0, evJoin, 0);
    k_gather<0><<<gGth, B>>>((const uint2*)hD, (float4*)aggD);

    // layer 1
    k_gemm<1><<<gGemm, B, GEMM_SMEM>>>(aggD, W1, hD, NN);
    k_gather<1><<<gGth, B>>>((const uint2*)hD, (float4*)out);
}

// round 15
// speedup vs baseline: 1.2968x; 1.0069x over previous
#include <cuda_runtime.h>
#include <cuda_fp16.h>
#include <math.h>

#define NN 50000
#define EE 600000
#define DD 128
#define ELLS 96                    // ELL row stride (max supported degree)

// ---------------- scratch (device globals; no allocation allowed) ----------
__device__ float g_deg[NN];
__device__ float g_dinv[NN];
__device__ int   g_cnt[NN];          // per-dst fill cursor / final count
__device__ uint2 g_cell[NN * ELLS];  // ELL slot: (src index, weight bits)
__device__ unsigned g_h16[NN * 64];  // raw messages h as half2 pairs
__device__ float g_agg[NN * DD];     // aggregated features (layer-0 output, f32)
__device__ float g_sc[2 * DD];       // folded BN scale per layer
__device__ float g_sh[2 * DD];       // folded BN shift (incl. bias) per layer
__device__ float g_alpha;            // sigmoid(act_params[0])

// ---------------- prep kernels ----------------------------------------------
__global__ void k_zero() {
    int i = blockIdx.x * blockDim.x + threadIdx.x;
    if (i < NN) {
        g_cnt[i] = 0;
        g_deg[i] = 0.f;
    }
}

// single edge pass: weighted degree + ELL fill (raw weight); ILP2
__global__ void k_degfill(const int* __restrict__ src, const int* __restrict__ dst,
                          const float* __restrict__ ew) {
    int t = blockIdx.x * blockDim.x + threadIdx.x;
    int stride = gridDim.x * blockDim.x;
    int   dd[2], ss[2];
    float ww[2];
    bool  vv[2];
#pragma unroll
    for (int i = 0; i < 2; i++) {
        int e = t + i * stride;
        vv[i] = (e < EE);
        if (vv[i]) {
            dd[i] = dst[e];
            ss[i] = src[e];
            ww[i] = ew[e];
        }
    }
#pragma unroll
    for (int i = 0; i < 2; i++) {
        if (vv[i]) {
            atomicAdd(&g_deg[dd[i]], ww[i]);
            int c = atomicAdd(&g_cnt[dd[i]], 1);
            if (c < ELLS)
                g_cell[dd[i] * ELLS + c] = make_uint2((unsigned)ss[i],
                                                      __float_as_uint(ww[i]));
        }
    }
}

// fused: dinv compute + store, and in-place slot normalization
__global__ void k_wnormF() {
    int t = blockIdx.x * blockDim.x + threadIdx.x;
    int node = t >> 5;
    int lane = t & 31;
    if (node >= NN) return;
    float dn = rsqrtf(g_deg[node] + 1.0f);   // +1 = self-loop weight
    if (lane == 0) g_dinv[node] = dn;
    int cnt = g_cnt[node];
    if (cnt > ELLS) cnt = ELLS;
    int beg = node * ELLS;
    for (int j = lane; j < cnt; j += 32) {
        uint2 cell = g_cell[beg + j];
        float w = __uint_as_float(cell.y) * dn *
                  rsqrtf(__ldg(&g_deg[cell.x]) + 1.0f);
        g_cell[beg + j].y = __float_as_uint(w);
    }
}

__global__ void k_bnprep(const float* __restrict__ b0, const float* __restrict__ ga0,
                         const float* __restrict__ be0, const float* __restrict__ m0,
                         const float* __restrict__ v0,
                         const float* __restrict__ b1, const float* __restrict__ ga1,
                         const float* __restrict__ be1, const float* __restrict__ m1,
                         const float* __restrict__ v1,
                         const float* __restrict__ act) {
    int t = threadIdx.x;
    if (t < DD) {
        float sc = ga0[t] * rsqrtf(v0[t] + 1e-5f);
        g_sc[t] = sc;
        g_sh[t] = be0[t] + (b0[t] - m0[t]) * sc;
    } else if (t < 2 * DD) {
        int c = t - DD;
        float sc = ga1[c] * rsqrtf(v1[c] + 1e-5f);
        g_sc[t] = sc;
        g_sh[t] = be1[c] + (b1[c] - m1[c]) * sc;
    }
    if (t == 0) g_alpha = 1.0f / (1.0f + expf(-act[0]));
}

// ---------------- fp16 tensor-core GEMM (ldmatrix mainloop) -----------------
// H16 = A' @ W with fp16 inputs, fp32 accumulate (mma.m16n8k16).
// A' = A (PRE_POST=0) or adaptive-act(BN0(A)) applied during staging.
// SMEM (32-bit words): As[64][68] (k halves packed), WsT[128][68] = W^T.
#define SMSW 68                                    // smem row stride (words)
#define GEMM_SMEM ((64 * SMSW + 128 * SMSW) * 4)   // 52.2 KB -> 4 blocks/SM

template <int PRE_POST>
__global__ __launch_bounds__(256, 4) void k_gemm(const float* __restrict__ A,
                                                 const float* __restrict__ W,
                                                 unsigned* __restrict__ H16, int n) {
    extern __shared__ unsigned sm[];
    unsigned* As  = sm;               // [64][SMSW]  A rows (k halves packed)
    unsigned* WsT = sm + 64 * SMSW;   // [128][SMSW] W^T: row n, k halves packed

    int tid = threadIdx.x;
    int row0 = blockIdx.x * 64;

    // ---- stage W transposed as half: WsT[n][k] ----
    const float4* W4 = (const float4*)W;
#pragma unroll
    for (int it = 0; it < 4; it++) {
        int task = tid + it * 256;      // 1024 tasks = 32 Rg x 32 Cg
        int Rg = task >> 5;             // k rows 4Rg..4Rg+3
        int Cg = task & 31;             // n cols 4Cg..4Cg+3
        float4 v0 = W4[(4 * Rg + 0) * 32 + Cg];
        float4 v1 = W4[(4 * Rg + 1) * 32 + Cg];
        float4 v2 = W4[(4 * Rg + 2) * 32 + Cg];
        float4 v3 = W4[(4 * Rg + 3) * 32 + Cg];
        const float* p0 = (const float*)&v0;
        const float* p1 = (const float*)&v1;
        const float* p2 = (const float*)&v2;
        const float* p3 = (const float*)&v3;
#pragma unroll
        for (int i = 0; i < 4; i++) {
            __half2 lo = __floats2half2_rn(p0[i], p1[i]);   // k = 4Rg, 4Rg+1
            __half2 hi = __floats2half2_rn(p2[i], p3[i]);   // k = 4Rg+2, 4Rg+3
            int base = (4 * Cg + i) * SMSW + 2 * Rg;
            WsT[base]     = *(unsigned*)&lo;
            WsT[base + 1] = *(unsigned*)&hi;
        }
    }

    // ---- stage A tile as half (+ fused BN0 + adaptive act for layer 1) ----
    float alpha = g_alpha;
    const float4* A4 = (const float4*)A;
#pragma unroll
    for (int i = 0; i < 8; i++) {
        int idx = tid + i * 256;        // 2048 float4 = 64 rows x 32
        int r = idx >> 5, c = idx & 31;
        float4 v = make_float4(0.f, 0.f, 0.f, 0.f);
        if (row0 + r < n) v = A4[(size_t)(row0 + r) * 32 + c];
        if (PRE_POST) {
            float* pv = (float*)&v;
#pragma unroll
            for (int j = 0; j < 4; j++) {
                float t = pv[j] * g_sc[c * 4 + j] + g_sh[c * 4 + j];
                float relu = fmaxf(t, 0.f);
                float gelu = 0.5f * t * (1.f + erff(t * 0.70710678118654752f));
                pv[j] = alpha * relu + (1.f - alpha) * gelu;
            }
        }
        __half2 h01 = __floats2half2_rn(v.x, v.y);
        __half2 h23 = __floats2half2_rn(v.z, v.w);
        uint2 pack = make_uint2(*(unsigned*)&h01, *(unsigned*)&h23);
        *(uint2*)&As[r * SMSW + 2 * c] = pack;
    }
    __syncthreads();

    int wid = tid >> 5;
    int lane = tid & 31;
    int rw = (wid & 3) * 16;       // row band within tile
    int cwb = (wid >> 2) * 64;     // col half

    // ldmatrix base addresses (byte addresses in shared space)
    // A x4: lanes 0-7 -> rows rw+0..7 @k0 ; 8-15 -> rows +8 @k0 ;
    //       16-23 -> rows rw+0..7 @k0+16B ; 24-31 -> rows +8 @k0+16B
    int arow = rw + (lane & 7) + ((lane >> 3) & 1) * 8;
    unsigned aBase = (unsigned)__cvta_generic_to_shared(As + arow * SMSW)
                   + ((lane >> 4) & 1) * 16;

    // B x4 per n-pair g: lanes 0-7 -> rows n0..n0+7 @k0 ; 8-15 -> same @k0+16B ;
    //                    16-23 -> rows n0+8.. @k0 ; 24-31 -> same @k0+16B
    unsigned bBase[4];
#pragma unroll
    for (int g = 0; g < 4; g++) {
        int brow = cwb + g * 16 + (lane & 7) + ((lane >> 4) & 1) * 8;
        bBase[g] = (unsigned)__cvta_generic_to_shared(WsT + brow * SMSW)
                 + ((lane >> 3) & 1) * 16;
    }

    float acc[8][4];
#pragma unroll
    for (int nt = 0; nt < 8; nt++)
#pragma unroll
        for (int j = 0; j < 4; j++) acc[nt][j] = 0.f;

#pragma unroll
    for (int kt = 0; kt < 8; kt++) {
        unsigned a0, a1, a2, a3;
        asm volatile("ldmatrix.sync.aligned.m8n8.x4.shared.b16 {%0,%1,%2,%3}, [%4];"
                     : "=r"(a0), "=r"(a1), "=r"(a2), "=r"(a3)
                     : "r"(aBase + kt * 32));
#pragma unroll
        for (int g = 0; g < 4; g++) {
            unsigned b0, b1, b2, b3;   // {b0,b1} for nt=2g, {b2,b3} for nt=2g+1
            asm volatile("ldmatrix.sync.aligned.m8n8.x4.shared.b16 {%0,%1,%2,%3}, [%4];"
                         : "=r"(b0), "=r"(b1), "=r"(b2), "=r"(b3)
                         : "r"(bBase[g] + kt * 32));
            asm("mma.sync.aligned.m16n8k16.row.col.f32.f16.f16.f32 "
                "{%0,%1,%2,%3}, {%4,%5,%6,%7}, {%8,%9}, {%0,%1,%2,%3};"
                : "+f"(acc[2 * g][0]), "+f"(acc[2 * g][1]),
                  "+f"(acc[2 * g][2]), "+f"(acc[2 * g][3])
                : "r"(a0), "r"(a1), "r"(a2), "r"(a3), "r"(b0), "r"(b1));
            asm("mma.sync.aligned.m16n8k16.row.col.f32.f16.f16.f32 "
                "{%0,%1,%2,%3}, {%4,%5,%6,%7}, {%8,%9}, {%0,%1,%2,%3};"
                : "+f"(acc[2 * g + 1][0]), "+f"(acc[2 * g + 1][1]),
                  "+f"(acc[2 * g + 1][2]), "+f"(acc[2 * g + 1][3])
                : "r"(a0), "r"(a1), "r"(a2), "r"(a3), "r"(b2), "r"(b3));
        }
    }

    // ---- epilogue: store raw fp16 message pairs ----
    int q = lane >> 2;             // 0..7
    int m = lane & 3;              // 0..3
    int r_lo = row0 + rw + q;      // rows r_lo and r_lo+8
#pragma unroll
    for (int nt = 0; nt < 8; nt++) {
        int col = cwb + nt * 8 + 2 * m;
        if (r_lo < n) {
            __half2 hv = __floats2half2_rn(acc[nt][0], acc[nt][1]);
            H16[(size_t)r_lo * 64 + (col >> 1)] = *(unsigned*)&hv;
        }
        if (r_lo + 8 < n) {
            __half2 hv = __floats2half2_rn(acc[nt][2], acc[nt][3]);
            H16[(size_t)(r_lo + 8) * 64 + (col >> 1)] = *(unsigned*)&hv;
        }
    }
}

// ---------------- gather: one warp per destination node --------------------
// acc = dinv^2 * m[node] + sum_j w_j * m[src_j]   (w fully normalized in cell)
// POST: apply BN1 before store.
template <int POST>
__global__ __launch_bounds__(256) void k_gather(const uint2* __restrict__ h,
                                                float4* __restrict__ out) {
    int t = blockIdx.x * blockDim.x + threadIdx.x;
    int node = t >> 5;
    int lane = t & 31;
    if (node >= NN) return;

    int beg = node * ELLS;
    int cnt = g_cnt[node];
    if (cnt > ELLS) cnt = ELLS;
    int end = beg + cnt;

    float d = g_dinv[node];
    d *= d;
    uint2 sr = h[(size_t)node * 32 + lane];
    float2 slo = __half22float2(*(__half2*)&sr.x);
    float2 shi = __half22float2(*(__half2*)&sr.y);
    float4 acc = make_float4(slo.x * d, slo.y * d, shi.x * d, shi.y * d);

    int j = beg;
    for (; j + 3 < end; j += 4) {
        uint2 e0 = __ldg(&g_cell[j]);
        uint2 e1 = __ldg(&g_cell[j + 1]);
        uint2 e2 = __ldg(&g_cell[j + 2]);
        uint2 e3 = __ldg(&g_cell[j + 3]);
        float w0 = __uint_as_float(e0.y);
        float w1 = __uint_as_float(e1.y);
        float w2 = __uint_as_float(e2.y);
        float w3 = __uint_as_float(e3.y);
        uint2 r0 = h[(size_t)e0.x * 32 + lane];
        uint2 r1 = h[(size_t)e1.x * 32 + lane];
        uint2 r2 = h[(size_t)e2.x * 32 + lane];
        uint2 r3 = h[(size_t)e3.x * 32 + lane];
        float2 l0 = __half22float2(*(__half2*)&r0.x), h0 = __half22float2(*(__half2*)&r0.y);
        float2 l1 = __half22float2(*(__half2*)&r1.x), h1 = __half22float2(*(__half2*)&r1.y);
        float2 l2 = __half22float2(*(__half2*)&r2.x), h2 = __half22float2(*(__half2*)&r2.y);
        float2 l3 = __half22float2(*(__half2*)&r3.x), h3 = __half22float2(*(__half2*)&r3.y);
        acc.x += w0 * l0.x + w1 * l1.x + w2 * l2.x + w3 * l3.x;
        acc.y += w0 * l0.y + w1 * l1.y + w2 * l2.y + w3 * l3.y;
        acc.z += w0 * h0.x + w1 * h1.x + w2 * h2.x + w3 * h3.x;
        acc.w += w0 * h0.y + w1 * h1.y + w2 * h2.y + w3 * h3.y;
    }
    for (; j < end; j++) {
        uint2 e = __ldg(&g_cell[j]);
        float w = __uint_as_float(e.y);
        uint2 r = h[(size_t)e.x * 32 + lane];
        float2 lo = __half22float2(*(__half2*)&r.x);
        float2 hi = __half22float2(*(__half2*)&r.y);
        acc.x += w * lo.x;
        acc.y += w * lo.y;
        acc.z += w * hi.x;
        acc.w += w * hi.y;
    }

    if (POST) {
        int c0 = lane * 4 + DD;   // layer-1 BN params
        acc.x = acc.x * g_sc[c0 + 0] + g_sh[c0 + 0];
        acc.y = acc.y * g_sc[c0 + 1] + g_sh[c0 + 1];
        acc.z = acc.z * g_sc[c0 + 2] + g_sh[c0 + 2];
        acc.w = acc.w * g_sc[c0 + 3] + g_sh[c0 + 3];
    }
    out[(size_t)node * 32 + lane] = acc;
}

// ---------------- launch ----------------------------------------------------
extern "C" void kernel_launch(void* const* d_in, const int* in_sizes, int n_in,
                              void* d_out, int out_size) {
    const float* x  = (const float*)d_in[0];
    const int*   ei = (const int*)d_in[1];     // [2,E]: row0=src, row1=dst
    const float* ew = (const float*)d_in[2];
    const float* W0 = (const float*)d_in[3];
    const float* b0 = (const float*)d_in[4];
    const float* W1 = (const float*)d_in[5];
    const float* b1 = (const float*)d_in[6];
    const float* ga0 = (const float*)d_in[7];
    const float* be0 = (const float*)d_in[8];
    const float* m0  = (const float*)d_in[9];
    const float* v0  = (const float*)d_in[10];
    const float* ga1 = (const float*)d_in[11];
    const float* be1 = (const float*)d_in[12];
    const float* m1  = (const float*)d_in[13];
    const float* v1  = (const float*)d_in[14];
    const float* act = (const float*)d_in[15];
    float* out = (float*)d_out;

    const int* src = ei;
    const int* dst = ei + EE;

    unsigned* hD; cudaGetSymbolAddress((void**)&hD, g_h16);
    float* aggD;  cudaGetSymbolAddress((void**)&aggD, g_agg);

    cudaFuncSetAttribute(k_gemm<0>, cudaFuncAttributeMaxDynamicSharedMemorySize, GEMM_SMEM);
    cudaFuncSetAttribute(k_gemm<1>, cudaFuncAttributeMaxDynamicSharedMemorySize, GEMM_SMEM);

    // side stream + fork/join events (created once; capture-safe fork pattern)
    static cudaStream_t sA = nullptr;
    static cudaEvent_t evFork = nullptr, evJoin = nullptr;
    if (sA == nullptr) {
        cudaStreamCreateWithFlags(&sA, cudaStreamNonBlocking);
        cudaEventCreateWithFlags(&evFork, cudaEventDisableTiming);
        cudaEventCreateWithFlags(&evJoin, cudaEventDisableTiming);
    }

    const int B = 256;
    int gN    = (NN + B - 1) / B;
    int gE2   = (EE + 2 * B - 1) / (2 * B);
    int gGth  = (NN * 32 + B - 1) / B;
    int gGemm = (NN + 63) / 64;

    // ---- main stream: zero first (both streams depend on it) ----
    k_zero<<<gN, B>>>();

    // ---- fork: graph prep on side stream, concurrent with layer-0 GEMM ----
    cudaEventRecord(evFork, 0);
    cudaStreamWaitEvent(sA, evFork, 0);
    k_degfill<<<gE2, B, 0, sA>>>(src, dst, ew);
    k_wnormF<<<gGth, B, 0, sA>>>();
    cudaEventRecord(evJoin, sA);

    // ---- main stream: layer-0 GEMM (graph-independent), then bn prep ----
    k_gemm<0><<<gGemm, B, GEMM_SMEM>>>(x, W0, hD, NN);
    k_bnprep<<<1, 256>>>(b0, ga0, be0, m0, v0, b1, ga1, be1, m1, v1, act);

    // ---- join: gather needs ELL + dinv ----
    cudaStreamWaitEvent(0, evJoin, 0);
    k_gather<0><<<gGth, B>>>((const uint2*)hD, (float4*)aggD);

    // layer 1
    k_gemm<1><<<gGemm, B, GEMM_SMEM>>>(aggD, W1, hD, NN);
    k_gather<1><<<gGth, B>>>((const uint2*)hD, (float4*)out);
}

// round 16
// speedup vs baseline: 1.3894x; 1.0714x over previous
#include <cuda_runtime.h>
#include <cuda_fp16.h>
#include <math.h>

#define NN 50000
#define EE 600000
#define DD 128
#define ELLS 96                    // ELL row stride (max supported degree)

// ---------------- scratch (device globals; no allocation allowed) ----------
__device__ float g_deg[NN];
__device__ float g_dinv[NN];
__device__ int   g_cnt[NN];          // per-dst fill cursor / final count
__device__ uint2 g_cell[NN * ELLS];  // ELL slot: (src index, weight bits)
__device__ unsigned g_h16[NN * 64];  // raw messages h as half2 pairs
__device__ float g_agg[NN * DD];     // aggregated features (layer-0 output, f32)
__device__ float g_sc[2 * DD];       // folded BN scale per layer
__device__ float g_sh[2 * DD];       // folded BN shift (incl. bias) per layer
__device__ float g_alpha;            // sigmoid(act_params[0])

// ---------------- prep kernels ----------------------------------------------
__global__ void k_zero() {
    int i = blockIdx.x * blockDim.x + threadIdx.x;
    if (i < NN) {
        g_cnt[i] = 0;
        g_deg[i] = 0.f;
    }
}

// single edge pass: weighted degree + ELL fill (raw weight); ILP2
__global__ void k_degfill(const int* __restrict__ src, const int* __restrict__ dst,
                          const float* __restrict__ ew) {
    int t = blockIdx.x * blockDim.x + threadIdx.x;
    int stride = gridDim.x * blockDim.x;
    int   dd[2], ss[2];
    float ww[2];
    bool  vv[2];
#pragma unroll
    for (int i = 0; i < 2; i++) {
        int e = t + i * stride;
        vv[i] = (e < EE);
        if (vv[i]) {
            dd[i] = dst[e];
            ss[i] = src[e];
            ww[i] = ew[e];
        }
    }
#pragma unroll
    for (int i = 0; i < 2; i++) {
        if (vv[i]) {
            atomicAdd(&g_deg[dd[i]], ww[i]);
            int c = atomicAdd(&g_cnt[dd[i]], 1);
            if (c < ELLS)
                g_cell[dd[i] * ELLS + c] = make_uint2((unsigned)ss[i],
                                                      __float_as_uint(ww[i]));
        }
    }
}

// fused: dinv compute + store, and in-place slot normalization
__global__ void k_wnormF() {
    int t = blockIdx.x * blockDim.x + threadIdx.x;
    int node = t >> 5;
    int lane = t & 31;
    if (node >= NN) return;
    float dn = rsqrtf(g_deg[node] + 1.0f);   // +1 = self-loop weight
    if (lane == 0) g_dinv[node] = dn;
    int cnt = g_cnt[node];
    if (cnt > ELLS) cnt = ELLS;
    int beg = node * ELLS;
    for (int j = lane; j < cnt; j += 32) {
        uint2 cell = g_cell[beg + j];
        float w = __uint_as_float(cell.y) * dn *
                  rsqrtf(__ldg(&g_deg[cell.x]) + 1.0f);
        g_cell[beg + j].y = __float_as_uint(w);
    }
}

__global__ void k_bnprep(const float* __restrict__ b0, const float* __restrict__ ga0,
                         const float* __restrict__ be0, const float* __restrict__ m0,
                         const float* __restrict__ v0,
                         const float* __restrict__ b1, const float* __restrict__ ga1,
                         const float* __restrict__ be1, const float* __restrict__ m1,
                         const float* __restrict__ v1,
                         const float* __restrict__ act) {
    int t = threadIdx.x;
    if (t < DD) {
        float sc = ga0[t] * rsqrtf(v0[t] + 1e-5f);
        g_sc[t] = sc;
        g_sh[t] = be0[t] + (b0[t] - m0[t]) * sc;
    } else if (t < 2 * DD) {
        int c = t - DD;
        float sc = ga1[c] * rsqrtf(v1[c] + 1e-5f);
        g_sc[t] = sc;
        g_sh[t] = be1[c] + (b1[c] - m1[c]) * sc;
    }
    if (t == 0) g_alpha = 1.0f / (1.0f + expf(-act[0]));
}

// ---------------- fp16 tensor-core GEMM (ldmatrix mainloop) -----------------
// H16 = A' @ W with fp16 inputs, fp32 accumulate (mma.m16n8k16).
// A' = A (PRE_POST=0) or adaptive-act(BN0(A)) applied during staging.
// SMEM (32-bit words): As[64][68] (k halves packed), Ws[128][68] natural [k][n]
// layout (n halves packed). B fragments come from ldmatrix.x4.trans — the
// staging stores are conflict-free (8B stores, 2-word stride).
#define SMSW 68                                    // smem row stride (words)
#define GEMM_SMEM ((64 * SMSW + 128 * SMSW) * 4)   // 52.2 KB -> 4 blocks/SM

template <int PRE_POST>
__global__ __launch_bounds__(256, 4) void k_gemm(const float* __restrict__ A,
                                                 const float* __restrict__ W,
                                                 unsigned* __restrict__ H16, int n) {
    extern __shared__ unsigned sm[];
    unsigned* As = sm;               // [64][SMSW]  A rows (k halves packed)
    unsigned* Ws = sm + 64 * SMSW;   // [128][SMSW] W natural: row k, n halves

    int tid = threadIdx.x;
    int row0 = blockIdx.x * 64;

    // ---- stage W natural [k][n] as half (coalesced loads, no-conflict stores)
    const float4* W4 = (const float4*)W;
#pragma unroll
    for (int i = 0; i < 16; i++) {
        int idx = tid + i * 256;        // 4096 float4 = 128 k-rows x 32
        int r = idx >> 5, c = idx & 31;
        float4 v = W4[idx];
        __half2 h01 = __floats2half2_rn(v.x, v.y);
        __half2 h23 = __floats2half2_rn(v.z, v.w);
        uint2 pack = make_uint2(*(unsigned*)&h01, *(unsigned*)&h23);
        *(uint2*)&Ws[r * SMSW + 2 * c] = pack;
    }

    // ---- stage A tile as half (+ fused BN0 + adaptive act for layer 1) ----
    float alpha = g_alpha;
    const float4* A4 = (const float4*)A;
#pragma unroll
    for (int i = 0; i < 8; i++) {
        int idx = tid + i * 256;        // 2048 float4 = 64 rows x 32
        int r = idx >> 5, c = idx & 31;
        float4 v = make_float4(0.f, 0.f, 0.f, 0.f);
        if (row0 + r < n) v = A4[(size_t)(row0 + r) * 32 + c];
        if (PRE_POST) {
            float* pv = (float*)&v;
#pragma unroll
            for (int j = 0; j < 4; j++) {
                float t = pv[j] * g_sc[c * 4 + j] + g_sh[c * 4 + j];
                float relu = fmaxf(t, 0.f);
                float gelu = 0.5f * t * (1.f + erff(t * 0.70710678118654752f));
                pv[j] = alpha * relu + (1.f - alpha) * gelu;
            }
        }
        __half2 h01 = __floats2half2_rn(v.x, v.y);
        __half2 h23 = __floats2half2_rn(v.z, v.w);
        uint2 pack = make_uint2(*(unsigned*)&h01, *(unsigned*)&h23);
        *(uint2*)&As[r * SMSW + 2 * c] = pack;
    }
    __syncthreads();

    int wid = tid >> 5;
    int lane = tid & 31;
    int rw = (wid & 3) * 16;       // row band within tile
    int cwb = (wid >> 2) * 64;     // col half

    // A x4 (non-trans): lanes 0-7 -> rows rw+0..7 @k0 ; 8-15 -> rows +8 ;
    //                   16-23 -> rows rw+0..7 @k0+16B ; 24-31 -> rows +8 @+16B
    int arow = rw + (lane & 7) + ((lane >> 3) & 1) * 8;
    unsigned aBase = (unsigned)__cvta_generic_to_shared(As + arow * SMSW)
                   + ((lane >> 4) & 1) * 16;

    // B x4 TRANS per n-group g (16 n-cols): rows = k (within kt), cols = n.
    // lanes 0-7  -> k rows k0..k0+7   @ n-off 0
    // lanes 8-15 -> k rows k0+8..+15  @ n-off 0
    // lanes 16-23-> k rows k0..k0+7   @ n-off 8 cols (16B)
    // lanes 24-31-> k rows k0+8..+15  @ n-off 8 cols
    // -> regs {r0,r1} = b0,b1 of n-tile 2g ; {r2,r3} = b0,b1 of n-tile 2g+1
    unsigned bBase[4];
#pragma unroll
    for (int g = 0; g < 4; g++) {
        int krow = (lane & 7) + ((lane >> 3) & 1) * 8;
        int ncol = cwb + g * 16 + ((lane >> 4) & 1) * 8;
        bBase[g] = (unsigned)__cvta_generic_to_shared(Ws + krow * SMSW)
                 + ncol * 2;
    }

    float acc[8][4];
#pragma unroll
    for (int nt = 0; nt < 8; nt++)
#pragma unroll
        for (int j = 0; j < 4; j++) acc[nt][j] = 0.f;

#pragma unroll
    for (int kt = 0; kt < 8; kt++) {
        unsigned a0, a1, a2, a3;
        asm volatile("ldmatrix.sync.aligned.m8n8.x4.shared.b16 {%0,%1,%2,%3}, [%4];"
                     : "=r"(a0), "=r"(a1), "=r"(a2), "=r"(a3)
                     : "r"(aBase + kt * 32));
        unsigned kOff = kt * 16 * SMSW * 4;   // advance 16 k-rows
#pragma unroll
        for (int g = 0; g < 4; g++) {
            unsigned b0, b1, b2, b3;
            asm volatile("ldmatrix.sync.aligned.m8n8.x4.trans.shared.b16 {%0,%1,%2,%3}, [%4];"
                         : "=r"(b0), "=r"(b1), "=r"(b2), "=r"(b3)
                         : "r"(bBase[g] + kOff));
            asm("mma.sync.aligned.m16n8k16.row.col.f32.f16.f16.f32 "
                "{%0,%1,%2,%3}, {%4,%5,%6,%7}, {%8,%9}, {%0,%1,%2,%3};"
                : "+f"(acc[2 * g][0]), "+f"(acc[2 * g][1]),
                  "+f"(acc[2 * g][2]), "+f"(acc[2 * g][3])
                : "r"(a0), "r"(a1), "r"(a2), "r"(a3), "r"(b0), "r"(b1));
            asm("mma.sync.aligned.m16n8k16.row.col.f32.f16.f16.f32 "
                "{%0,%1,%2,%3}, {%4,%5,%6,%7}, {%8,%9}, {%0,%1,%2,%3};"
                : "+f"(acc[2 * g + 1][0]), "+f"(acc[2 * g + 1][1]),
                  "+f"(acc[2 * g + 1][2]), "+f"(acc[2 * g + 1][3])
                : "r"(a0), "r"(a1), "r"(a2), "r"(a3), "r"(b2), "r"(b3));
        }
    }

    // ---- epilogue: store raw fp16 message pairs ----
    int q = lane >> 2;             // 0..7
    int m = lane & 3;              // 0..3
    int r_lo = row0 + rw + q;      // rows r_lo and r_lo+8
#pragma unroll
    for (int nt = 0; nt < 8; nt++) {
        int col = cwb + nt * 8 + 2 * m;
        if (r_lo < n) {
            __half2 hv = __floats2half2_rn(acc[nt][0], acc[nt][1]);
            H16[(size_t)r_lo * 64 + (col >> 1)] = *(unsigned*)&hv;
        }
        if (r_lo + 8 < n) {
            __half2 hv = __floats2half2_rn(acc[nt][2], acc[nt][3]);
            H16[(size_t)(r_lo + 8) * 64 + (col >> 1)] = *(unsigned*)&hv;
        }
    }
}

// ---------------- gather: one warp per destination node --------------------
// acc = dinv^2 * m[node] + sum_j w_j * m[src_j]   (w fully normalized in cell)
// POST: apply BN1 before store.
template <int POST>
__global__ __launch_bounds__(256) void k_gather(const uint2* __restrict__ h,
                                                float4* __restrict__ out) {
    int t = blockIdx.x * blockDim.x + threadIdx.x;
    int node = t >> 5;
    int lane = t & 31;
    if (node >= NN) return;

    int beg = node * ELLS;
    int cnt = g_cnt[node];
    if (cnt > ELLS) cnt = ELLS;
    int end = beg + cnt;

    float d = g_dinv[node];
    d *= d;
    uint2 sr = h[(size_t)node * 32 + lane];
    float2 slo = __half22float2(*(__half2*)&sr.x);
    float2 shi = __half22float2(*(__half2*)&sr.y);
    float4 acc = make_float4(slo.x * d, slo.y * d, shi.x * d, shi.y * d);

    int j = beg;
    for (; j + 3 < end; j += 4) {
        uint2 e0 = __ldg(&g_cell[j]);
        uint2 e1 = __ldg(&g_cell[j + 1]);
        uint2 e2 = __ldg(&g_cell[j + 2]);
        uint2 e3 = __ldg(&g_cell[j + 3]);
        float w0 = __uint_as_float(e0.y);
        float w1 = __uint_as_float(e1.y);
        float w2 = __uint_as_float(e2.y);
        float w3 = __uint_as_float(e3.y);
        uint2 r0 = h[(size_t)e0.x * 32 + lane];
        uint2 r1 = h[(size_t)e1.x * 32 + lane];
        uint2 r2 = h[(size_t)e2.x * 32 + lane];
        uint2 r3 = h[(size_t)e3.x * 32 + lane];
        float2 l0 = __half22float2(*(__half2*)&r0.x), h0 = __half22float2(*(__half2*)&r0.y);
        float2 l1 = __half22float2(*(__half2*)&r1.x), h1 = __half22float2(*(__half2*)&r1.y);
        float2 l2 = __half22float2(*(__half2*)&r2.x), h2 = __half22float2(*(__half2*)&r2.y);
        float2 l3 = __half22float2(*(__half2*)&r3.x), h3 = __half22float2(*(__half2*)&r3.y);
        acc.x += w0 * l0.x + w1 * l1.x + w2 * l2.x + w3 * l3.x;
        acc.y += w0 * l0.y + w1 * l1.y + w2 * l2.y + w3 * l3.y;
        acc.z += w0 * h0.x + w1 * h1.x + w2 * h2.x + w3 * h3.x;
        acc.w += w0 * h0.y + w1 * h1.y + w2 * h2.y + w3 * h3.y;
    }
    for (; j < end; j++) {
        uint2 e = __ldg(&g_cell[j]);
        float w = __uint_as_float(e.y);
        uint2 r = h[(size_t)e.x * 32 + lane];
        float2 lo = __half22float2(*(__half2*)&r.x);
        float2 hi = __half22float2(*(__half2*)&r.y);
        acc.x += w * lo.x;
        acc.y += w * lo.y;
        acc.z += w * hi.x;
        acc.w += w * hi.y;
    }

    if (POST) {
        int c0 = lane * 4 + DD;   // layer-1 BN params
        acc.x = acc.x * g_sc[c0 + 0] + g_sh[c0 + 0];
        acc.y = acc.y * g_sc[c0 + 1] + g_sh[c0 + 1];
        acc.z = acc.z * g_sc[c0 + 2] + g_sh[c0 + 2];
        acc.w = acc.w * g_sc[c0 + 3] + g_sh[c0 + 3];
    }
    out[(size_t)node * 32 + lane] = acc;
}

// ---------------- launch ----------------------------------------------------
extern "C" void kernel_launch(void* const* d_in, const int* in_sizes, int n_in,
                              void* d_out, int out_size) {
    const float* x  = (const float*)d_in[0];
    const int*   ei = (const int*)d_in[1];     // [2,E]: row0=src, row1=dst
    const float* ew = (const float*)d_in[2];
    const float* W0 = (const float*)d_in[3];
    const float* b0 = (const float*)d_in[4];
    const float* W1 = (const float*)d_in[5];
    const float* b1 = (const float*)d_in[6];
    const float* ga0 = (const float*)d_in[7];
    const float* be0 = (const float*)d_in[8];
    const float* m0  = (const float*)d_in[9];
    const float* v0  = (const float*)d_in[10];
    const float* ga1 = (const float*)d_in[11];
    const float* be1 = (const float*)d_in[12];
    const float* m1  = (const float*)d_in[13];
    const float* v1  = (const float*)d_in[14];
    const float* act = (const float*)d_in[15];
    float* out = (float*)d_out;

    const int* src = ei;
    const int* dst = ei + EE;

    unsigned* hD; cudaGetSymbolAddress((void**)&hD, g_h16);
    float* aggD;  cudaGetSymbolAddress((void**)&aggD, g_agg);

    cudaFuncSetAttribute(k_gemm<0>, cudaFuncAttributeMaxDynamicSharedMemorySize, GEMM_SMEM);
    cudaFuncSetAttribute(k_gemm<1>, cudaFuncAttributeMaxDynamicSharedMemorySize, GEMM_SMEM);

    // side stream + fork/join events (created once; capture-safe fork pattern)
    static cudaStream_t sA = nullptr;
    static cudaEvent_t evFork = nullptr, evJoin = nullptr;
    if (sA == nullptr) {
        cudaStreamCreateWithFlags(&sA, cudaStreamNonBlocking);
        cudaEventCreateWithFlags(&evFork, cudaEventDisableTiming);
        cudaEventCreateWithFlags(&evJoin, cudaEventDisableTiming);
    }

    const int B = 256;
    int gN    = (NN + B - 1) / B;
    int gE2   = (EE + 2 * B - 1) / (2 * B);
    int gGth  = (NN * 32 + B - 1) / B;
    int gGemm = (NN + 63) / 64;

    // ---- main stream: zero first (both streams depend on it) ----
    k_zero<<<gN, B>>>();

    // ---- fork: graph prep on side stream, concurrent with layer-0 GEMM ----
    cudaEventRecord(evFork, 0);
    cudaStreamWaitEvent(sA, evFork, 0);
    k_degfill<<<gE2, B, 0, sA>>>(src, dst, ew);
    k_wnormF<<<gGth, B, 0, sA>>>();
    cudaEventRecord(evJoin, sA);

    // ---- main stream: layer-0 GEMM (graph-independent), then bn prep ----
    k_gemm<0><<<gGemm, B, GEMM_SMEM>>>(x, W0, hD, NN);
    k_bnprep<<<1, 256>>>(b0, ga0, be0, m0, v0, b1, ga1, be1, m1, v1, act);

    // ---- join: gather needs ELL + dinv ----
    cudaStreamWaitEvent(0, evJoin, 0);
    k_gather<0><<<gGth, B>>>((const uint2*)hD, (float4*)aggD);

    // layer 1
    k_gemm<1><<<gGemm, B, GEMM_SMEM>>>(aggD, W1, hD, NN);
    k_gather<1><<<gGth, B>>>((const uint2*)hD, (float4*)out);
}